// round 11
// baseline (speedup 1.0000x reference)
#include <cuda_runtime.h>
#include <cuda_bf16.h>
#include <cstdint>

#define NN   50000
#define NPAD 50048              // 391 * 128
#define HID  128
#define NREL 8
#define KC   64
#define NCH  2                  // 128/64
#define NMB  391                // M blocks
#define NSUB 8
#define NB2  (NMB * NREL * NSUB)    // 25024 buckets
#define EMAX 600000
#define ECAP 1024
#define ND   (NREL * HID + HID)     // 1152

// ---------------- scratch ----------------
__device__ float g_t[(size_t)NPAD * HID];
__device__ float g_inv[(size_t)NN * NREL];
__device__ float g_bt1[ND * HID];    // B^T [1152][128] fp32, tf32-rounded
__device__ float g_bt2[ND * HID];
__device__ int g_hist[NB2];
__device__ int g_cur[NB2];
__device__ int g_boff[NB2 + 1];
__device__ int4 g_edge[EMAX];        // (src, dst, scale_bits, 0), bucket-sorted

// ---------------- helpers ----------------
__device__ __forceinline__ void ldmx4(uint32_t* r, uint32_t addr) {
    asm volatile("ldmatrix.sync.aligned.m8n8.x4.shared.b16 {%0,%1,%2,%3}, [%4];"
                 : "=r"(r[0]), "=r"(r[1]), "=r"(r[2]), "=r"(r[3]) : "r"(addr));
}
__device__ __forceinline__ void mma_tf32(float* c, const uint32_t* a, const uint32_t* b) {
    asm volatile("mma.sync.aligned.m16n8k8.row.col.f32.tf32.tf32.f32 "
                 "{%0,%1,%2,%3}, {%4,%5,%6,%7}, {%8,%9}, {%0,%1,%2,%3};"
                 : "+f"(c[0]), "+f"(c[1]), "+f"(c[2]), "+f"(c[3])
                 : "r"(a[0]), "r"(a[1]), "r"(a[2]), "r"(a[3]), "r"(b[0]), "r"(b[1]));
}
__device__ __forceinline__ uint32_t f2tf32(float f) {
    uint32_t r;
    asm("cvt.rna.tf32.f32 %0, %1;" : "=r"(r) : "f"(f));
    return r;
}
__device__ __forceinline__ uint32_t smem_u32(const void* p) {
    uint32_t a;
    asm("{ .reg .u64 t; cvta.to.shared.u64 t, %1; cvt.u32.u64 %0, t; }" : "=r"(a) : "l"(p));
    return a;
}
__device__ __forceinline__ void cp_async16(uint32_t saddr, const void* gaddr) {
    asm volatile("cp.async.cg.shared.global [%0], [%1], 16;" :: "r"(saddr), "l"(gaddr));
}
__device__ __forceinline__ void red_add_f32(float* p, float v) {
    asm volatile("red.global.add.f32 [%0], %1;" :: "l"(p), "f"(v) : "memory");
}
__device__ __forceinline__ void red_add_s32(int* p, int v) {
    asm volatile("red.global.add.s32 [%0], %1;" :: "l"(p), "r"(v) : "memory");
}

// ---------------- small kernels ----------------
__global__ void counthist_kernel(const int* __restrict__ src, const int* __restrict__ dst,
                                 const int* __restrict__ rel, int E,
                                 float* __restrict__ cnt, int* __restrict__ hist) {
    int base = (blockIdx.x * blockDim.x + threadIdx.x) * 4;
#pragma unroll
    for (int i = 0; i < 4; i++) {
        int e = base + i;
        if (e < E) {
            int s = __ldg(src + e);
            int r = __ldg(rel + e);
            red_add_f32(&cnt[__ldg(dst + e) * NREL + r], 1.0f);
            red_add_s32(&hist[((s >> 7) * NREL + r) * NSUB + ((s >> 4) & 7)], 1);
        }
    }
}
__global__ void inv_kernel(float* __restrict__ cnt, int n) {
    int i = blockIdx.x * blockDim.x + threadIdx.x;
    if (i < n) cnt[i] = 1.0f / fmaxf(cnt[i], 1.0f);
}
#define VPT 25
__global__ void scan_kernel(const int* __restrict__ hist, int* __restrict__ boff) {
    __shared__ int part[1024];
    int t = threadIdx.x;
    int vals[VPT];
    int s = 0;
#pragma unroll
    for (int i = 0; i < VPT; i++) {
        int b = t * VPT + i;
        vals[i] = (b < NB2) ? hist[b] : 0;
        s += vals[i];
    }
    part[t] = s;
    __syncthreads();
    for (int off = 1; off < 1024; off <<= 1) {
        int v = (t >= off) ? part[t - off] : 0;
        __syncthreads();
        part[t] += v;
        __syncthreads();
    }
    int run = (t > 0) ? part[t - 1] : 0;
#pragma unroll
    for (int i = 0; i < VPT; i++) {
        int b = t * VPT + i;
        if (b <= NB2) boff[b] = run;
        run += vals[i];
    }
    if (t == 1023) boff[NB2] = run;
}
__global__ void reorder_kernel(const int* __restrict__ src, const int* __restrict__ dst,
                               const int* __restrict__ rel, int E,
                               const int* __restrict__ boff, int* __restrict__ cur,
                               const float* __restrict__ inv, int4* __restrict__ edge) {
    int base = (blockIdx.x * blockDim.x + threadIdx.x) * 4;
    int s[4], d[4], r[4], pos[4];
    float sc[4];
    int n = min(4, E - base);
    if (n <= 0) return;
#pragma unroll
    for (int i = 0; i < 4; i++) {
        if (i < n) {
            s[i] = __ldg(src + base + i);
            d[i] = __ldg(dst + base + i);
            r[i] = __ldg(rel + base + i);
        }
    }
#pragma unroll
    for (int i = 0; i < 4; i++) {
        if (i < n) {
            int b = ((s[i] >> 7) * NREL + r[i]) * NSUB + ((s[i] >> 4) & 7);
            pos[i] = __ldg(boff + b) + atomicAdd(&cur[b], 1);
            sc[i] = __ldg(inv + d[i] * NREL + r[i]);
        }
    }
#pragma unroll
    for (int i = 0; i < 4; i++)
        if (i < n) edge[pos[i]] = make_int4(s[i], d[i], __float_as_int(sc[i]), 0);
}
// B^T[nn][k] fp32, tf32-rounded: nn<1024 -> W[nn>>7,k,nn&127]; else root[k,nn-1024]
__global__ void bconv_kernel(const float* __restrict__ W, const float* __restrict__ root,
                             float* __restrict__ bt) {
    int i = blockIdx.x * blockDim.x + threadIdx.x;
    if (i >= ND * HID) return;
    int nn = i >> 7, k = i & 127;
    float v = (nn < NREL * HID) ? W[((size_t)(nn >> 7) * HID + k) * HID + (nn & 127)]
                                : root[(size_t)k * HID + (nn - NREL * HID)];
    bt[i] = __int_as_float(f2tf32(v));
}
__global__ void binit_kernel(float* __restrict__ acc, const float* __restrict__ bias, int rows) {
    int i = blockIdx.x * blockDim.x + threadIdx.x;
    if (i >= rows * 32) return;
    ((float4*)acc)[i] = ((const float4*)bias)[i & 31];
}

// ---------------- fused tf32 GEMM + scatter ----------------
// grid (9, 391); smem 80KB: A 32KB fp32(tf32), B 32KB fp32(tf32) [both reused as stile],
// edges 16KB at 64KB. Rows of 256B, swizzle kb ^ ((row&7)*16).
__global__ void __launch_bounds__(256, 2)
gemm_fused(const float* __restrict__ X, int xrows, int do_relu,
           const float* __restrict__ Bt,
           float* __restrict__ acc_out, int acc_rows,
           const int4* __restrict__ edge, const int* __restrict__ boff) {
    extern __shared__ char smem[];
    const uint32_t sbase = smem_u32(smem);
    const uint32_t A_OF = 0, B_OF = 32768, EDG = 65536;
    float* stile = (float*)smem;
    const int4* sedge = (const int4*)(smem + EDG);

    const int tid = threadIdx.x, wid = tid >> 5, lid = tid & 31;
    const int nt = blockIdx.x;                 // 0..7 relations, 8 root
    const int block_row = blockIdx.y * 128;
    const int bcol = nt * 128;
    const int wm = wid >> 2, wn = wid & 3;

    // edge prefetch (relation tiles only)
    int e0 = 0, ecnt = 0;
    if (nt < 8) {
        const int b8 = (blockIdx.y * NREL + nt) * NSUB;
        e0 = boff[b8];
        ecnt = boff[b8 + NSUB] - e0;
        int pn = min(ecnt, ECAP);
        for (int i = tid; i < pn; i += 256)
            cp_async16(sbase + EDG + i * 16, edge + e0 + i);
    }
    asm volatile("cp.async.commit_group;" ::: "memory");

    // per-lane ldmatrix geometry (x4, non-trans)
    const int mquad = lid >> 3;                 // which of 4 matrices this lane addresses
    const uint32_t axor = (uint32_t)(lid & 7) * 16;
    // A: matrices = {rows 0-7, rows 8-15} x {k 0-3, k 4-7}
    const uint32_t a_base = (uint32_t)(wm * 64 + (mquad & 1) * 8 + (lid & 7)) * 256;
    const uint32_t a_kb = (uint32_t)(mquad >> 1) * 16;
    // B: matrices = {h0 k0-3, h0 k4-7, h1 k0-3, h1 k4-7}
    const uint32_t b_base = (uint32_t)(wn * 32 + (mquad >> 1) * 8 + (lid & 7)) * 256;
    const uint32_t b_kb = (uint32_t)(mquad & 1) * 16;

    float acc[4][4][4];
#pragma unroll
    for (int i = 0; i < 4; i++)
#pragma unroll
        for (int j = 0; j < 4; j++)
#pragma unroll
            for (int v = 0; v < 4; v++) acc[i][j][v] = 0.0f;

    for (int c = 0; c < NCH; c++) {
        // ---- B: straight cp.async copy (pre-rounded tf32), swizzled dst ----
#pragma unroll
        for (int i = 0; i < 8; i++) {
            int idx = tid + i * 256;            // 0..2047
            int n = idx >> 4;
            int k16 = idx & 15;
            uint32_t dst = sbase + B_OF + (uint32_t)n * 256
                         + (((uint32_t)k16 * 16) ^ ((uint32_t)(n & 7) * 16));
            cp_async16(dst, Bt + (size_t)(bcol + n) * HID + c * KC + k16 * 4);
        }
        asm volatile("cp.async.commit_group;" ::: "memory");

        // ---- A: fp32 load + relu + tf32 round, swizzled store ----
#pragma unroll
        for (int i = 0; i < 8; i++) {
            int idx = tid + i * 256;            // 0..2047
            int row = idx >> 4;
            int k4 = (idx & 15) * 4;
            int grow = block_row + row;
            float4 v = make_float4(0.f, 0.f, 0.f, 0.f);
            if (grow < xrows) v = *(const float4*)(X + (size_t)grow * HID + c * KC + k4);
            if (do_relu) {
                v.x = fmaxf(v.x, 0.f); v.y = fmaxf(v.y, 0.f);
                v.z = fmaxf(v.z, 0.f); v.w = fmaxf(v.w, 0.f);
            }
            uint4 t;
            t.x = f2tf32(v.x); t.y = f2tf32(v.y); t.z = f2tf32(v.z); t.w = f2tf32(v.w);
            uint32_t sw = (uint32_t)row * 256
                        + (((uint32_t)k4 * 4) ^ ((uint32_t)(row & 7) * 16));
            *(uint4*)(smem + A_OF + sw) = t;
        }
        asm volatile("cp.async.wait_group 0;" ::: "memory");
        __syncthreads();

        // ---- compute: 8 k8 steps, 16 tf32 MMAs each ----
#pragma unroll
        for (int s = 0; s < 8; s++) {
            uint32_t af[4][4], bf[4][2];
            uint32_t skb = (uint32_t)s * 32;
#pragma unroll
            for (int mt = 0; mt < 4; mt++)
                ldmx4(af[mt], sbase + A_OF + a_base + (uint32_t)mt * 4096
                              + ((skb + a_kb) ^ axor));
#pragma unroll
            for (int p = 0; p < 2; p++) {
                uint32_t r4[4];
                ldmx4(r4, sbase + B_OF + b_base + (uint32_t)p * 4096
                          + ((skb + b_kb) ^ axor));
                bf[2 * p][0] = r4[0]; bf[2 * p][1] = r4[1];
                bf[2 * p + 1][0] = r4[2]; bf[2 * p + 1][1] = r4[3];
            }
#pragma unroll
            for (int mt = 0; mt < 4; mt++)
#pragma unroll
                for (int j = 0; j < 4; j++) mma_tf32(acc[mt][j], af[mt], bf[j]);
        }
        __syncthreads();
    }

    if (nt == 8) {
        // root tile: red.add into pre-biased accumulator
#pragma unroll
        for (int mt = 0; mt < 4; mt++) {
            int r0 = block_row + wm * 64 + mt * 16 + (lid >> 2);
#pragma unroll
            for (int j = 0; j < 4; j++) {
                int col = wn * 32 + j * 8 + (lid & 3) * 2;
                if (r0 < acc_rows) {
                    float* p = acc_out + (size_t)r0 * HID + col;
                    asm volatile("red.global.add.v2.f32 [%0], {%1, %2};"
                                 :: "l"(p), "f"(acc[mt][j][0]), "f"(acc[mt][j][1]) : "memory");
                }
                if (r0 + 8 < acc_rows) {
                    float* p = acc_out + (size_t)(r0 + 8) * HID + col;
                    asm volatile("red.global.add.v2.f32 [%0], {%1, %2};"
                                 :: "l"(p), "f"(acc[mt][j][2]), "f"(acc[mt][j][3]) : "memory");
                }
            }
        }
        return;
    }

    // relation tile: stage fp32 tile to smem, scatter bucket edges
#pragma unroll
    for (int mt = 0; mt < 4; mt++) {
        int r0 = wm * 64 + mt * 16 + (lid >> 2);
#pragma unroll
        for (int j = 0; j < 4; j++) {
            int col = wn * 32 + j * 8 + (lid & 3) * 2;
            *(float2*)(stile + r0 * 128 + col)       = make_float2(acc[mt][j][0], acc[mt][j][1]);
            *(float2*)(stile + (r0 + 8) * 128 + col) = make_float2(acc[mt][j][2], acc[mt][j][3]);
        }
    }
    __syncthreads();

    const int pn = min(ecnt, ECAP);
    for (int e = wid; e < pn; e += 8) {
        int4 ed = sedge[e];
        float sc = __int_as_float(ed.z);
        const float4 v = *(const float4*)(stile + (ed.x - block_row) * 128 + lid * 4);
        float4* p = (float4*)(acc_out + (size_t)ed.y * HID) + lid;
        asm volatile("red.global.add.v4.f32 [%0], {%1, %2, %3, %4};"
                     :: "l"(p), "f"(v.x * sc), "f"(v.y * sc), "f"(v.z * sc), "f"(v.w * sc)
                     : "memory");
    }
    for (int e = ECAP + wid; e < ecnt; e += 8) {
        int4 ed = edge[e0 + e];
        float sc = __int_as_float(ed.z);
        const float4 v = *(const float4*)(stile + (ed.x - block_row) * 128 + lid * 4);
        float4* p = (float4*)(acc_out + (size_t)ed.y * HID) + lid;
        asm volatile("red.global.add.v4.f32 [%0], {%1, %2, %3, %4};"
                     :: "l"(p), "f"(v.x * sc), "f"(v.y * sc), "f"(v.z * sc), "f"(v.w * sc)
                     : "memory");
    }
}

// ---------------- launch ----------------
extern "C" void kernel_launch(void* const* d_in, const int* in_sizes, int n_in,
                              void* d_out, int out_size) {
    const int* edge_index = (const int*)d_in[0];
    const int* edge_type  = (const int*)d_in[1];
    const float* node_emb = (const float*)d_in[2];
    const float* W1    = (const float*)d_in[3];
    const float* root1 = (const float*)d_in[4];
    const float* b1    = (const float*)d_in[5];
    const float* W2    = (const float*)d_in[6];
    const float* root2 = (const float*)d_in[7];
    const float* b2    = (const float*)d_in[8];
    float* out = (float*)d_out;

    const int E = in_sizes[0] / 2;
    const int* src = edge_index;
    const int* dst = edge_index + E;

    float *t, *inv, *bt1, *bt2;
    int *hist, *cur, *boff;
    int4* edge;
    cudaGetSymbolAddress((void**)&t,    g_t);
    cudaGetSymbolAddress((void**)&inv,  g_inv);
    cudaGetSymbolAddress((void**)&bt1,  g_bt1);
    cudaGetSymbolAddress((void**)&bt2,  g_bt2);
    cudaGetSymbolAddress((void**)&hist, g_hist);
    cudaGetSymbolAddress((void**)&cur,  g_cur);
    cudaGetSymbolAddress((void**)&boff, g_boff);
    cudaGetSymbolAddress((void**)&edge, g_edge);

    const int T = 256;
    const dim3 gemm_grid(9, NMB);
    const int SMEM_BYTES = 65536 + ECAP * 16;   // 81920
    cudaFuncSetAttribute(gemm_fused, cudaFuncAttributeMaxDynamicSharedMemorySize, SMEM_BYTES);

    // ---- prep ----
    cudaMemsetAsync(inv, 0, sizeof(float) * (size_t)NN * NREL, 0);
    cudaMemsetAsync(hist, 0, sizeof(int) * NB2, 0);
    cudaMemsetAsync(cur, 0, sizeof(int) * NB2, 0);
    counthist_kernel<<<(E + T * 4 - 1) / (T * 4), T>>>(src, dst, edge_type, E, inv, hist);
    inv_kernel<<<(NN * NREL + T - 1) / T, T>>>(inv, NN * NREL);
    scan_kernel<<<1, 1024>>>(hist, boff);
    reorder_kernel<<<(E + T * 4 - 1) / (T * 4), T>>>(src, dst, edge_type, E, boff, cur,
                                                     inv, edge);
    bconv_kernel<<<(ND * HID + T - 1) / T, T>>>(W1, root1, bt1);
    bconv_kernel<<<(ND * HID + T - 1) / T, T>>>(W2, root2, bt2);
    binit_kernel<<<(NPAD * 32 + T - 1) / T, T>>>(t, b1, NPAD);
    binit_kernel<<<(NN * 32 + T - 1) / T, T>>>(out, b2, NN);

    // ---- layer 1: A = node_emb (no relu), accumulate into t ----
    gemm_fused<<<gemm_grid, T, SMEM_BYTES>>>(node_emb, NN, 0, bt1, t, NPAD, edge, boff);
    // ---- layer 2: A = relu(t), accumulate into out ----
    gemm_fused<<<gemm_grid, T, SMEM_BYTES>>>(t, NPAD, 1, bt2, out, NN, edge, boff);
}

// round 12
// speedup vs baseline: 1.0871x; 1.0871x over previous
#include <cuda_runtime.h>
#include <cuda_bf16.h>
#include <cstdint>

#define NN   50000
#define NPAD 50048              // 391 * 128
#define HID  128
#define NREL 8
#define KC   64
#define NCH  2                  // 128/64
#define NMB  391
#define NSUB 8
#define NB2  (NMB * NREL * NSUB)    // 25024 buckets
#define EMAX 600000
#define ECAP 512                // smem edge records per (block, rel)
#define ND   (NREL * HID + HID)

// ---------------- scratch ----------------
__device__ float g_t[(size_t)NPAD * HID];
__device__ float g_cnt[(size_t)NN * NREL];
__device__ __nv_bfloat16 g_bhi1[ND * HID];
__device__ __nv_bfloat16 g_blo1[ND * HID];
__device__ __nv_bfloat16 g_bhi2[ND * HID];
__device__ __nv_bfloat16 g_blo2[ND * HID];
__device__ int g_hist[NB2];
__device__ int g_cur[NB2];
__device__ int g_boff[NB2 + 1];
__device__ int4 g_edge[EMAX];    // (src, dst, scale_bits, 0), bucket-sorted

// ---------------- helpers ----------------
__device__ __forceinline__ void ldmx4(uint32_t* r, uint32_t addr) {
    asm volatile("ldmatrix.sync.aligned.m8n8.x4.shared.b16 {%0,%1,%2,%3}, [%4];"
                 : "=r"(r[0]), "=r"(r[1]), "=r"(r[2]), "=r"(r[3]) : "r"(addr));
}
__device__ __forceinline__ void mma16816(float* c, const uint32_t* a, const uint32_t* b) {
    asm volatile("mma.sync.aligned.m16n8k16.row.col.f32.bf16.bf16.f32 "
                 "{%0,%1,%2,%3}, {%4,%5,%6,%7}, {%8,%9}, {%0,%1,%2,%3};"
                 : "+f"(c[0]), "+f"(c[1]), "+f"(c[2]), "+f"(c[3])
                 : "r"(a[0]), "r"(a[1]), "r"(a[2]), "r"(a[3]), "r"(b[0]), "r"(b[1]));
}
__device__ __forceinline__ uint32_t smem_u32(const void* p) {
    uint32_t a;
    asm("{ .reg .u64 t; cvta.to.shared.u64 t, %1; cvt.u32.u64 %0, t; }" : "=r"(a) : "l"(p));
    return a;
}
__device__ __forceinline__ void cp_async16(uint32_t saddr, const void* gaddr) {
    asm volatile("cp.async.cg.shared.global [%0], [%1], 16;" :: "r"(saddr), "l"(gaddr));
}
__device__ __forceinline__ void red_add_f32(float* p, float v) {
    asm volatile("red.global.add.f32 [%0], %1;" :: "l"(p), "f"(v) : "memory");
}
__device__ __forceinline__ void red_add_s32(int* p, int v) {
    asm volatile("red.global.add.s32 [%0], %1;" :: "l"(p), "r"(v) : "memory");
}

// ---------------- small kernels ----------------
__global__ void counthist_kernel(const int* __restrict__ src, const int* __restrict__ dst,
                                 const int* __restrict__ rel, int E,
                                 float* __restrict__ cnt, int* __restrict__ hist) {
    int base = (blockIdx.x * blockDim.x + threadIdx.x) * 4;
#pragma unroll
    for (int i = 0; i < 4; i++) {
        int e = base + i;
        if (e < E) {
            int s = __ldg(src + e);
            int r = __ldg(rel + e);
            red_add_f32(&cnt[__ldg(dst + e) * NREL + r], 1.0f);
            red_add_s32(&hist[((s >> 7) * NREL + r) * NSUB + ((s >> 4) & 7)], 1);
        }
    }
}
#define VPT 25
__global__ void scan_kernel(const int* __restrict__ hist, int* __restrict__ boff) {
    __shared__ int part[1024];
    int t = threadIdx.x;
    int vals[VPT];
    int s = 0;
#pragma unroll
    for (int i = 0; i < VPT; i++) {
        int b = t * VPT + i;
        vals[i] = (b < NB2) ? hist[b] : 0;
        s += vals[i];
    }
    part[t] = s;
    __syncthreads();
    for (int off = 1; off < 1024; off <<= 1) {
        int v = (t >= off) ? part[t - off] : 0;
        __syncthreads();
        part[t] += v;
        __syncthreads();
    }
    int run = (t > 0) ? part[t - 1] : 0;
#pragma unroll
    for (int i = 0; i < VPT; i++) {
        int b = t * VPT + i;
        if (b <= NB2) boff[b] = run;
        run += vals[i];
    }
    if (t == 1023) boff[NB2] = run;
}
// emits (src, dst, 1/max(cnt,1), 0); inv computation fused
__global__ void reorder_kernel(const int* __restrict__ src, const int* __restrict__ dst,
                               const int* __restrict__ rel, int E,
                               const int* __restrict__ boff, int* __restrict__ cur,
                               const float* __restrict__ cnt, int4* __restrict__ edge) {
    int base = (blockIdx.x * blockDim.x + threadIdx.x) * 4;
    int s[4], d[4], r[4], pos[4];
    float sc[4];
    int n = min(4, E - base);
    if (n <= 0) return;
#pragma unroll
    for (int i = 0; i < 4; i++) {
        if (i < n) {
            s[i] = __ldg(src + base + i);
            d[i] = __ldg(dst + base + i);
            r[i] = __ldg(rel + base + i);
        }
    }
#pragma unroll
    for (int i = 0; i < 4; i++) {
        if (i < n) {
            int b = ((s[i] >> 7) * NREL + r[i]) * NSUB + ((s[i] >> 4) & 7);
            pos[i] = __ldg(boff + b) + atomicAdd(&cur[b], 1);
            sc[i] = 1.0f / fmaxf(__ldg(cnt + d[i] * NREL + r[i]), 1.0f);
        }
    }
#pragma unroll
    for (int i = 0; i < 4; i++)
        if (i < n) edge[pos[i]] = make_int4(s[i], d[i], __float_as_int(sc[i]), 0);
}
__global__ void bconv_kernel(const float* __restrict__ W, const float* __restrict__ root,
                             __nv_bfloat16* __restrict__ bhi, __nv_bfloat16* __restrict__ blo) {
    int i = blockIdx.x * blockDim.x + threadIdx.x;
    if (i >= ND * HID) return;
    int nn = i >> 7, k = i & 127;
    float v = (nn < NREL * HID) ? W[((size_t)(nn >> 7) * HID + k) * HID + (nn & 127)]
                                : root[(size_t)k * HID + (nn - NREL * HID)];
    __nv_bfloat16 h = __float2bfloat16(v);
    bhi[i] = h;
    blo[i] = __float2bfloat16(v - __bfloat162float(h));
}
__global__ void binit_kernel(float* __restrict__ acc, const float* __restrict__ bias, int rows) {
    int i = blockIdx.x * blockDim.x + threadIdx.x;
    if (i >= rows * 32) return;
    ((float4*)acc)[i] = ((const float4*)bias)[i & 31];
}

// ---------------- fused bf16x3 GEMM (pipelined) + scatter ----------------
// smem 104KB: A_HI 16K @0, A_LO 16K @16K, B buf0 32K @32K, B buf1 32K @64K, edges 8K @96K.
// stile (fp32 128x128 = 64KB) reuses first 64KB after compute.
__global__ void __launch_bounds__(256, 2)
gemm_fused(const float* __restrict__ X, int xrows, int do_relu,
           const __nv_bfloat16* __restrict__ Bhi, const __nv_bfloat16* __restrict__ Blo,
           float* __restrict__ acc_out, int acc_rows,
           const int4* __restrict__ edge, const int* __restrict__ boff) {
    extern __shared__ char smem[];
    const uint32_t sbase = smem_u32(smem);
    const uint32_t A_HI = 0, A_LO = 16384, B_BUF0 = 32768, EDG = 98304;
    float* stile = (float*)smem;
    const int4* sedge = (const int4*)(smem + EDG);

    const int tid = threadIdx.x, wid = tid >> 5, lid = tid & 31;
    const int nt = blockIdx.x;                 // 0..7 relations, 8 root
    const int block_row = blockIdx.y * 128;
    const int bcol = nt * 128;
    const int wm = wid >> 2, wn = wid & 3;

    // ---- edge prefetch (relation tiles only) ----
    int e0 = 0, ecnt = 0;
    if (nt < 8) {
        const int b8 = (blockIdx.y * NREL + nt) * NSUB;
        e0 = boff[b8];
        ecnt = boff[b8 + NSUB] - e0;
        int pn = min(ecnt, ECAP);
        for (int i = tid; i < pn; i += 256)
            cp_async16(sbase + EDG + i * 16, edge + e0 + i);
    }

    // ---- B chunk0 -> buf0 via cp.async ----
#pragma unroll
    for (int i = 0; i < 8; i++) {
        int idx = tid + i * 256;                // 0..2047
        int buf = idx >> 10;                    // 0=hi 1=lo
        int r = (idx >> 3) & 127;
        int k16 = idx & 7;
        const __nv_bfloat16* srcb = buf ? Blo : Bhi;
        uint32_t sw = (uint32_t)r * 128 + (((uint32_t)k16 * 16) ^ ((uint32_t)(r & 7) * 16));
        cp_async16(sbase + B_BUF0 + (uint32_t)buf * 16384 + sw,
                   srcb + (size_t)(bcol + r) * HID + k16 * 8);
    }
    asm volatile("cp.async.commit_group;" ::: "memory");

    const int arow = (lid & 15);
    const uint32_t akoff = (uint32_t)(lid >> 4) * 16;
    const uint32_t axor = (uint32_t)(arow & 7) * 16;
    const int brow = (lid & 7) + ((lid >> 4) * 8);
    const uint32_t bkoff = (uint32_t)((lid >> 3) & 1) * 16;
    const uint32_t bxor = (uint32_t)(brow & 7) * 16;

    float acc[4][4][4];
#pragma unroll
    for (int i = 0; i < 4; i++)
#pragma unroll
        for (int j = 0; j < 4; j++)
#pragma unroll
            for (int v = 0; v < 4; v++) acc[i][j][v] = 0.0f;

    // ---- stage A chunk0 (overlaps with cp.async above) ----
#pragma unroll
    for (int i = 0; i < 8; i++) {
        int idx = tid + i * 256;
        int row = idx >> 4;
        int k4 = (idx & 15) * 4;
        int grow = block_row + row;
        float4 v = make_float4(0.f, 0.f, 0.f, 0.f);
        if (grow < xrows) v = *(const float4*)(X + (size_t)grow * HID + k4);
        if (do_relu) {
            v.x = fmaxf(v.x, 0.f); v.y = fmaxf(v.y, 0.f);
            v.z = fmaxf(v.z, 0.f); v.w = fmaxf(v.w, 0.f);
        }
        __nv_bfloat162 h01 = __floats2bfloat162_rn(v.x, v.y);
        __nv_bfloat162 h23 = __floats2bfloat162_rn(v.z, v.w);
        __nv_bfloat162 l01 = __floats2bfloat162_rn(v.x - __bfloat162float(h01.x),
                                                   v.y - __bfloat162float(h01.y));
        __nv_bfloat162 l23 = __floats2bfloat162_rn(v.z - __bfloat162float(h23.x),
                                                   v.w - __bfloat162float(h23.y));
        uint32_t sw = (uint32_t)row * 128 + (((uint32_t)k4 * 2) ^ ((uint32_t)(row & 7) * 16));
        uint2 hv, lv;
        hv.x = *(const uint32_t*)&h01; hv.y = *(const uint32_t*)&h23;
        lv.x = *(const uint32_t*)&l01; lv.y = *(const uint32_t*)&l23;
        *(uint2*)(smem + A_HI + sw) = hv;
        *(uint2*)(smem + A_LO + sw) = lv;
    }
    asm volatile("cp.async.wait_group 0;" ::: "memory");
    __syncthreads();

    for (int c = 0; c < NCH; c++) {
        const uint32_t B_HI = B_BUF0 + (uint32_t)(c & 1) * 32768;
        const uint32_t B_LO = B_HI + 16384;

        // issue next chunk's B copy BEFORE compute so it overlaps MMA
        if (c + 1 < NCH) {
            const uint32_t B_NXT = B_BUF0 + (uint32_t)((c + 1) & 1) * 32768;
#pragma unroll
            for (int i = 0; i < 8; i++) {
                int idx = tid + i * 256;
                int buf = idx >> 10;
                int r = (idx >> 3) & 127;
                int k16 = idx & 7;
                const __nv_bfloat16* srcb = buf ? Blo : Bhi;
                uint32_t sw = (uint32_t)r * 128
                            + (((uint32_t)k16 * 16) ^ ((uint32_t)(r & 7) * 16));
                cp_async16(sbase + B_NXT + (uint32_t)buf * 16384 + sw,
                           srcb + (size_t)(bcol + r) * HID + (c + 1) * KC + k16 * 8);
            }
            asm volatile("cp.async.commit_group;" ::: "memory");
        }

        // ---- compute chunk c: 4 k16 steps x 3 terms ----
#pragma unroll
        for (int kk = 0; kk < 4; kk++) {
            uint32_t af[4][4], bf[4][2];
            uint32_t ak = (uint32_t)kk * 32 + akoff;
            uint32_t bk = (uint32_t)kk * 32 + bkoff;

#pragma unroll
            for (int mt = 0; mt < 4; mt++) {
                uint32_t off = (uint32_t)(wm * 64 + mt * 16 + arow) * 128 + (ak ^ axor);
                ldmx4(af[mt], sbase + A_HI + off);
            }
#pragma unroll
            for (int p = 0; p < 2; p++) {
                uint32_t r4[4];
                uint32_t off = (uint32_t)(wn * 32 + p * 16 + brow) * 128 + (bk ^ bxor);
                ldmx4(r4, sbase + B_LO + off);
                bf[2 * p][0] = r4[0]; bf[2 * p][1] = r4[1];
                bf[2 * p + 1][0] = r4[2]; bf[2 * p + 1][1] = r4[3];
            }
#pragma unroll
            for (int mt = 0; mt < 4; mt++)
#pragma unroll
                for (int j = 0; j < 4; j++) mma16816(acc[mt][j], af[mt], bf[j]);

#pragma unroll
            for (int p = 0; p < 2; p++) {
                uint32_t r4[4];
                uint32_t off = (uint32_t)(wn * 32 + p * 16 + brow) * 128 + (bk ^ bxor);
                ldmx4(r4, sbase + B_HI + off);
                bf[2 * p][0] = r4[0]; bf[2 * p][1] = r4[1];
                bf[2 * p + 1][0] = r4[2]; bf[2 * p + 1][1] = r4[3];
            }
#pragma unroll
            for (int mt = 0; mt < 4; mt++)
#pragma unroll
                for (int j = 0; j < 4; j++) mma16816(acc[mt][j], af[mt], bf[j]);

#pragma unroll
            for (int mt = 0; mt < 4; mt++) {
                uint32_t off = (uint32_t)(wm * 64 + mt * 16 + arow) * 128 + (ak ^ axor);
                ldmx4(af[mt], sbase + A_LO + off);
            }
#pragma unroll
            for (int mt = 0; mt < 4; mt++)
#pragma unroll
                for (int j = 0; j < 4; j++) mma16816(acc[mt][j], af[mt], bf[j]);
        }

        // ---- restage A for next chunk (single A buffer) ----
        if (c + 1 < NCH) {
            __syncthreads();   // all warps done reading A chunk c
#pragma unroll
            for (int i = 0; i < 8; i++) {
                int idx = tid + i * 256;
                int row = idx >> 4;
                int k4 = (idx & 15) * 4;
                int grow = block_row + row;
                float4 v = make_float4(0.f, 0.f, 0.f, 0.f);
                if (grow < xrows)
                    v = *(const float4*)(X + (size_t)grow * HID + (c + 1) * KC + k4);
                if (do_relu) {
                    v.x = fmaxf(v.x, 0.f); v.y = fmaxf(v.y, 0.f);
                    v.z = fmaxf(v.z, 0.f); v.w = fmaxf(v.w, 0.f);
                }
                __nv_bfloat162 h01 = __floats2bfloat162_rn(v.x, v.y);
                __nv_bfloat162 h23 = __floats2bfloat162_rn(v.z, v.w);
                __nv_bfloat162 l01 = __floats2bfloat162_rn(v.x - __bfloat162float(h01.x),
                                                           v.y - __bfloat162float(h01.y));
                __nv_bfloat162 l23 = __floats2bfloat162_rn(v.z - __bfloat162float(h23.x),
                                                           v.w - __bfloat162float(h23.y));
                uint32_t sw = (uint32_t)row * 128
                            + (((uint32_t)k4 * 2) ^ ((uint32_t)(row & 7) * 16));
                uint2 hv, lv;
                hv.x = *(const uint32_t*)&h01; hv.y = *(const uint32_t*)&h23;
                lv.x = *(const uint32_t*)&l01; lv.y = *(const uint32_t*)&l23;
                *(uint2*)(smem + A_HI + sw) = hv;
                *(uint2*)(smem + A_LO + sw) = lv;
            }
            asm volatile("cp.async.wait_group 0;" ::: "memory");
            __syncthreads();
        }
    }

    if (nt == 8) {
#pragma unroll
        for (int mt = 0; mt < 4; mt++) {
            int r0 = block_row + wm * 64 + mt * 16 + (lid >> 2);
#pragma unroll
            for (int j = 0; j < 4; j++) {
                int col = wn * 32 + j * 8 + (lid & 3) * 2;
                if (r0 < acc_rows) {
                    float* p = acc_out + (size_t)r0 * HID + col;
                    asm volatile("red.global.add.v2.f32 [%0], {%1, %2};"
                                 :: "l"(p), "f"(acc[mt][j][0]), "f"(acc[mt][j][1]) : "memory");
                }
                if (r0 + 8 < acc_rows) {
                    float* p = acc_out + (size_t)(r0 + 8) * HID + col;
                    asm volatile("red.global.add.v2.f32 [%0], {%1, %2};"
                                 :: "l"(p), "f"(acc[mt][j][2]), "f"(acc[mt][j][3]) : "memory");
                }
            }
        }
        return;
    }

    // relation tile: stage fp32 tile to smem (reuses first 64KB), scatter bucket edges
    __syncthreads();
#pragma unroll
    for (int mt = 0; mt < 4; mt++) {
        int r0 = wm * 64 + mt * 16 + (lid >> 2);
#pragma unroll
        for (int j = 0; j < 4; j++) {
            int col = wn * 32 + j * 8 + (lid & 3) * 2;
            *(float2*)(stile + r0 * 128 + col)       = make_float2(acc[mt][j][0], acc[mt][j][1]);
            *(float2*)(stile + (r0 + 8) * 128 + col) = make_float2(acc[mt][j][2], acc[mt][j][3]);
        }
    }
    __syncthreads();

    const int pn = min(ecnt, ECAP);
    for (int e = wid; e < pn; e += 8) {
        int4 ed = sedge[e];
        float sc = __int_as_float(ed.z);
        const float4 v = *(const float4*)(stile + (ed.x - block_row) * 128 + lid * 4);
        float4* p = (float4*)(acc_out + (size_t)ed.y * HID) + lid;
        asm volatile("red.global.add.v4.f32 [%0], {%1, %2, %3, %4};"
                     :: "l"(p), "f"(v.x * sc), "f"(v.y * sc), "f"(v.z * sc), "f"(v.w * sc)
                     : "memory");
    }
    for (int e = ECAP + wid; e < ecnt; e += 8) {
        int4 ed = edge[e0 + e];
        float sc = __int_as_float(ed.z);
        const float4 v = *(const float4*)(stile + (ed.x - block_row) * 128 + lid * 4);
        float4* p = (float4*)(acc_out + (size_t)ed.y * HID) + lid;
        asm volatile("red.global.add.v4.f32 [%0], {%1, %2, %3, %4};"
                     :: "l"(p), "f"(v.x * sc), "f"(v.y * sc), "f"(v.z * sc), "f"(v.w * sc)
                     : "memory");
    }
}

// ---------------- launch ----------------
extern "C" void kernel_launch(void* const* d_in, const int* in_sizes, int n_in,
                              void* d_out, int out_size) {
    const int* edge_index = (const int*)d_in[0];
    const int* edge_type  = (const int*)d_in[1];
    const float* node_emb = (const float*)d_in[2];
    const float* W1    = (const float*)d_in[3];
    const float* root1 = (const float*)d_in[4];
    const float* b1    = (const float*)d_in[5];
    const float* W2    = (const float*)d_in[6];
    const float* root2 = (const float*)d_in[7];
    const float* b2    = (const float*)d_in[8];
    float* out = (float*)d_out;

    const int E = in_sizes[0] / 2;
    const int* src = edge_index;
    const int* dst = edge_index + E;

    float *t, *cnt;
    __nv_bfloat16 *bhi1, *blo1, *bhi2, *blo2;
    int *hist, *cur, *boff;
    int4* edge;
    cudaGetSymbolAddress((void**)&t,    g_t);
    cudaGetSymbolAddress((void**)&cnt,  g_cnt);
    cudaGetSymbolAddress((void**)&bhi1, g_bhi1);
    cudaGetSymbolAddress((void**)&blo1, g_blo1);
    cudaGetSymbolAddress((void**)&bhi2, g_bhi2);
    cudaGetSymbolAddress((void**)&blo2, g_blo2);
    cudaGetSymbolAddress((void**)&hist, g_hist);
    cudaGetSymbolAddress((void**)&cur,  g_cur);
    cudaGetSymbolAddress((void**)&boff, g_boff);
    cudaGetSymbolAddress((void**)&edge, g_edge);

    const int T = 256;
    const dim3 gemm_grid(9, NMB);
    const int SMEM_BYTES = 98304 + ECAP * 16;   // 106496
    cudaFuncSetAttribute(gemm_fused, cudaFuncAttributeMaxDynamicSharedMemorySize, SMEM_BYTES);

    // ---- prep ----
    cudaMemsetAsync(cnt, 0, sizeof(float) * (size_t)NN * NREL, 0);
    cudaMemsetAsync(hist, 0, sizeof(int) * NB2, 0);
    cudaMemsetAsync(cur, 0, sizeof(int) * NB2, 0);
    counthist_kernel<<<(E + T * 4 - 1) / (T * 4), T>>>(src, dst, edge_type, E, cnt, hist);
    scan_kernel<<<1, 1024>>>(hist, boff);
    reorder_kernel<<<(E + T * 4 - 1) / (T * 4), T>>>(src, dst, edge_type, E, boff, cur,
                                                     cnt, edge);
    bconv_kernel<<<(ND * HID + T - 1) / T, T>>>(W1, root1, bhi1, blo1);
    bconv_kernel<<<(ND * HID + T - 1) / T, T>>>(W2, root2, bhi2, blo2);
    binit_kernel<<<(NPAD * 32 + T - 1) / T, T>>>(t, b1, NPAD);
    binit_kernel<<<(NN * 32 + T - 1) / T, T>>>(out, b2, NN);

    // ---- layer 1: A = node_emb (no relu), accumulate into t ----
    gemm_fused<<<gemm_grid, T, SMEM_BYTES>>>(node_emb, NN, 0, bhi1, blo1,
                                             t, NPAD, edge, boff);
    // ---- layer 2: A = relu(t), accumulate into out ----
    gemm_fused<<<gemm_grid, T, SMEM_BYTES>>>(t, NPAD, 1, bhi2, blo2,
                                             out, NN, edge, boff);
}

// round 13
// speedup vs baseline: 1.1039x; 1.0155x over previous
#include <cuda_runtime.h>
#include <cuda_bf16.h>
#include <cstdint>

#define NN   50000
#define NPAD 50048              // 391 * 128
#define HID  128
#define NREL 8
#define KC   64
#define NCH  2                  // 128/64
#define NMB  391
#define NSUB 8
#define NB2  (NMB * NREL * NSUB)    // 25024 buckets
#define EMAX 600000
#define ECAP 512                // smem edge records per (block, rel)
#define ND   (NREL * HID + HID)

// ---------------- scratch ----------------
__device__ float g_t[(size_t)NPAD * HID];
__device__ float g_cnt[(size_t)NN * NREL];
__device__ __nv_bfloat16 g_bhi1[ND * HID];
__device__ __nv_bfloat16 g_blo1[ND * HID];
__device__ __nv_bfloat16 g_bhi2[ND * HID];
__device__ __nv_bfloat16 g_blo2[ND * HID];
__device__ int g_hist[NB2];
__device__ int g_cur[NB2];
__device__ int g_boff[NB2 + 1];
__device__ int4 g_edge[EMAX];    // (src, dst, scale_bits, 0), bucket-sorted

// ---------------- helpers ----------------
__device__ __forceinline__ void ldmx4(uint32_t* r, uint32_t addr) {
    asm volatile("ldmatrix.sync.aligned.m8n8.x4.shared.b16 {%0,%1,%2,%3}, [%4];"
                 : "=r"(r[0]), "=r"(r[1]), "=r"(r[2]), "=r"(r[3]) : "r"(addr));
}
__device__ __forceinline__ void mma16816(float* c, const uint32_t* a, const uint32_t* b) {
    asm volatile("mma.sync.aligned.m16n8k16.row.col.f32.bf16.bf16.f32 "
                 "{%0,%1,%2,%3}, {%4,%5,%6,%7}, {%8,%9}, {%0,%1,%2,%3};"
                 : "+f"(c[0]), "+f"(c[1]), "+f"(c[2]), "+f"(c[3])
                 : "r"(a[0]), "r"(a[1]), "r"(a[2]), "r"(a[3]), "r"(b[0]), "r"(b[1]));
}
__device__ __forceinline__ uint32_t smem_u32(const void* p) {
    uint32_t a;
    asm("{ .reg .u64 t; cvta.to.shared.u64 t, %1; cvt.u32.u64 %0, t; }" : "=r"(a) : "l"(p));
    return a;
}
__device__ __forceinline__ void cp_async16(uint32_t saddr, const void* gaddr) {
    asm volatile("cp.async.cg.shared.global [%0], [%1], 16;" :: "r"(saddr), "l"(gaddr));
}
__device__ __forceinline__ void red_add_f32(float* p, float v) {
    asm volatile("red.global.add.f32 [%0], %1;" :: "l"(p), "f"(v) : "memory");
}
__device__ __forceinline__ void red_add_s32(int* p, int v) {
    asm volatile("red.global.add.s32 [%0], %1;" :: "l"(p), "r"(v) : "memory");
}

// ---------------- small kernels ----------------
__global__ void counthist_kernel(const int* __restrict__ src, const int* __restrict__ dst,
                                 const int* __restrict__ rel, int E,
                                 float* __restrict__ cnt, int* __restrict__ hist) {
    int base = (blockIdx.x * blockDim.x + threadIdx.x) * 4;
#pragma unroll
    for (int i = 0; i < 4; i++) {
        int e = base + i;
        if (e < E) {
            int s = __ldg(src + e);
            int r = __ldg(rel + e);
            red_add_f32(&cnt[__ldg(dst + e) * NREL + r], 1.0f);
            red_add_s32(&hist[((s >> 7) * NREL + r) * NSUB + ((s >> 4) & 7)], 1);
        }
    }
}
#define VPT 25
__global__ void scan_kernel(const int* __restrict__ hist, int* __restrict__ boff) {
    __shared__ int part[1024];
    int t = threadIdx.x;
    int vals[VPT];
    int s = 0;
#pragma unroll
    for (int i = 0; i < VPT; i++) {
        int b = t * VPT + i;
        vals[i] = (b < NB2) ? hist[b] : 0;
        s += vals[i];
    }
    part[t] = s;
    __syncthreads();
    for (int off = 1; off < 1024; off <<= 1) {
        int v = (t >= off) ? part[t - off] : 0;
        __syncthreads();
        part[t] += v;
        __syncthreads();
    }
    int run = (t > 0) ? part[t - 1] : 0;
#pragma unroll
    for (int i = 0; i < VPT; i++) {
        int b = t * VPT + i;
        if (b <= NB2) boff[b] = run;
        run += vals[i];
    }
    if (t == 1023) boff[NB2] = run;
}
// 2 edges/thread (more resident warps); emits (src, dst, 1/max(cnt,1), 0)
__global__ void reorder_kernel(const int* __restrict__ src, const int* __restrict__ dst,
                               const int* __restrict__ rel, int E,
                               const int* __restrict__ boff, int* __restrict__ cur,
                               const float* __restrict__ cnt, int4* __restrict__ edge) {
    int base = (blockIdx.x * blockDim.x + threadIdx.x) * 2;
    int s[2], d[2], r[2], pos[2];
    float sc[2];
    int n = min(2, E - base);
    if (n <= 0) return;
#pragma unroll
    for (int i = 0; i < 2; i++) {
        if (i < n) {
            s[i] = __ldg(src + base + i);
            d[i] = __ldg(dst + base + i);
            r[i] = __ldg(rel + base + i);
        }
    }
#pragma unroll
    for (int i = 0; i < 2; i++) {
        if (i < n) {
            int b = ((s[i] >> 7) * NREL + r[i]) * NSUB + ((s[i] >> 4) & 7);
            pos[i] = __ldg(boff + b) + atomicAdd(&cur[b], 1);
            sc[i] = 1.0f / fmaxf(__ldg(cnt + d[i] * NREL + r[i]), 1.0f);
        }
    }
#pragma unroll
    for (int i = 0; i < 2; i++)
        if (i < n) edge[pos[i]] = make_int4(s[i], d[i], __float_as_int(sc[i]), 0);
}

// merged: bconv(W1), bconv(W2), binit(t, b1), binit(out, b2) — concurrent in one launch
#define BCONV_BLKS ((ND * HID + 255) / 256)       // 576
#define BINIT_T_BLKS ((NPAD * 32 + 255) / 256)    // 6256
#define BINIT_O_BLKS ((NN * 32 + 255) / 256)      // 6250
__global__ void prep_kernel(const float* __restrict__ W1, const float* __restrict__ root1,
                            const float* __restrict__ W2, const float* __restrict__ root2,
                            const float* __restrict__ b1, const float* __restrict__ b2,
                            __nv_bfloat16* __restrict__ bhi1, __nv_bfloat16* __restrict__ blo1,
                            __nv_bfloat16* __restrict__ bhi2, __nv_bfloat16* __restrict__ blo2,
                            float* __restrict__ t, float* __restrict__ out) {
    int bx = blockIdx.x;
    if (bx < 2 * BCONV_BLKS) {
        int layer = bx >= BCONV_BLKS;
        const float* W = layer ? W2 : W1;
        const float* root = layer ? root2 : root1;
        __nv_bfloat16* bhi = layer ? bhi2 : bhi1;
        __nv_bfloat16* blo = layer ? blo2 : blo1;
        int i = (bx - layer * BCONV_BLKS) * 256 + threadIdx.x;
        if (i >= ND * HID) return;
        int nn = i >> 7, k = i & 127;
        float v = (nn < NREL * HID) ? W[((size_t)(nn >> 7) * HID + k) * HID + (nn & 127)]
                                    : root[(size_t)k * HID + (nn - NREL * HID)];
        __nv_bfloat16 h = __float2bfloat16(v);
        bhi[i] = h;
        blo[i] = __float2bfloat16(v - __bfloat162float(h));
        return;
    }
    bx -= 2 * BCONV_BLKS;
    if (bx < BINIT_T_BLKS) {
        int i = bx * 256 + threadIdx.x;
        if (i < NPAD * 32) ((float4*)t)[i] = ((const float4*)b1)[i & 31];
        return;
    }
    bx -= BINIT_T_BLKS;
    int i = bx * 256 + threadIdx.x;
    if (i < NN * 32) ((float4*)out)[i] = ((const float4*)b2)[i & 31];
}

// ---------------- fused bf16x3 GEMM (pipelined) + scatter ----------------
// smem 104KB: A_HI 16K @0, A_LO 16K @16K, B buf0 32K @32K, B buf1 32K @64K, edges 8K @96K.
// stile (fp32 128x128 = 64KB) reuses first 64KB after compute.
__global__ void __launch_bounds__(256, 2)
gemm_fused(const float* __restrict__ X, int xrows, int do_relu,
           const __nv_bfloat16* __restrict__ Bhi, const __nv_bfloat16* __restrict__ Blo,
           float* __restrict__ acc_out, int acc_rows,
           const int4* __restrict__ edge, const int* __restrict__ boff) {
    extern __shared__ char smem[];
    const uint32_t sbase = smem_u32(smem);
    const uint32_t A_HI = 0, A_LO = 16384, B_BUF0 = 32768, EDG = 98304;
    float* stile = (float*)smem;
    const int4* sedge = (const int4*)(smem + EDG);

    const int tid = threadIdx.x, wid = tid >> 5, lid = tid & 31;
    const int nt = blockIdx.x;                 // 0..7 relations, 8 root
    const int block_row = blockIdx.y * 128;
    const int bcol = nt * 128;
    const int wm = wid >> 2, wn = wid & 3;

    // ---- edge prefetch (relation tiles only) ----
    int e0 = 0, ecnt = 0;
    if (nt < 8) {
        const int b8 = (blockIdx.y * NREL + nt) * NSUB;
        e0 = boff[b8];
        ecnt = boff[b8 + NSUB] - e0;
        int pn = min(ecnt, ECAP);
        for (int i = tid; i < pn; i += 256)
            cp_async16(sbase + EDG + i * 16, edge + e0 + i);
    }

    // ---- B chunk0 -> buf0 via cp.async ----
#pragma unroll
    for (int i = 0; i < 8; i++) {
        int idx = tid + i * 256;                // 0..2047
        int buf = idx >> 10;                    // 0=hi 1=lo
        int r = (idx >> 3) & 127;
        int k16 = idx & 7;
        const __nv_bfloat16* srcb = buf ? Blo : Bhi;
        uint32_t sw = (uint32_t)r * 128 + (((uint32_t)k16 * 16) ^ ((uint32_t)(r & 7) * 16));
        cp_async16(sbase + B_BUF0 + (uint32_t)buf * 16384 + sw,
                   srcb + (size_t)(bcol + r) * HID + k16 * 8);
    }
    asm volatile("cp.async.commit_group;" ::: "memory");

    const int arow = (lid & 15);
    const uint32_t akoff = (uint32_t)(lid >> 4) * 16;
    const uint32_t axor = (uint32_t)(arow & 7) * 16;
    const int brow = (lid & 7) + ((lid >> 4) * 8);
    const uint32_t bkoff = (uint32_t)((lid >> 3) & 1) * 16;
    const uint32_t bxor = (uint32_t)(brow & 7) * 16;

    float acc[4][4][4];
#pragma unroll
    for (int i = 0; i < 4; i++)
#pragma unroll
        for (int j = 0; j < 4; j++)
#pragma unroll
            for (int v = 0; v < 4; v++) acc[i][j][v] = 0.0f;

    // ---- stage A chunk0 (overlaps with cp.async above) ----
#pragma unroll
    for (int i = 0; i < 8; i++) {
        int idx = tid + i * 256;
        int row = idx >> 4;
        int k4 = (idx & 15) * 4;
        int grow = block_row + row;
        float4 v = make_float4(0.f, 0.f, 0.f, 0.f);
        if (grow < xrows) v = *(const float4*)(X + (size_t)grow * HID + k4);
        if (do_relu) {
            v.x = fmaxf(v.x, 0.f); v.y = fmaxf(v.y, 0.f);
            v.z = fmaxf(v.z, 0.f); v.w = fmaxf(v.w, 0.f);
        }
        __nv_bfloat162 h01 = __floats2bfloat162_rn(v.x, v.y);
        __nv_bfloat162 h23 = __floats2bfloat162_rn(v.z, v.w);
        __nv_bfloat162 l01 = __floats2bfloat162_rn(v.x - __bfloat162float(h01.x),
                                                   v.y - __bfloat162float(h01.y));
        __nv_bfloat162 l23 = __floats2bfloat162_rn(v.z - __bfloat162float(h23.x),
                                                   v.w - __bfloat162float(h23.y));
        uint32_t sw = (uint32_t)row * 128 + (((uint32_t)k4 * 2) ^ ((uint32_t)(row & 7) * 16));
        uint2 hv, lv;
        hv.x = *(const uint32_t*)&h01; hv.y = *(const uint32_t*)&h23;
        lv.x = *(const uint32_t*)&l01; lv.y = *(const uint32_t*)&l23;
        *(uint2*)(smem + A_HI + sw) = hv;
        *(uint2*)(smem + A_LO + sw) = lv;
    }
    asm volatile("cp.async.wait_group 0;" ::: "memory");
    __syncthreads();

    for (int c = 0; c < NCH; c++) {
        const uint32_t B_HI = B_BUF0 + (uint32_t)(c & 1) * 32768;
        const uint32_t B_LO = B_HI + 16384;

        // issue next chunk's B copy BEFORE compute so it overlaps MMA
        if (c + 1 < NCH) {
            const uint32_t B_NXT = B_BUF0 + (uint32_t)((c + 1) & 1) * 32768;
#pragma unroll
            for (int i = 0; i < 8; i++) {
                int idx = tid + i * 256;
                int buf = idx >> 10;
                int r = (idx >> 3) & 127;
                int k16 = idx & 7;
                const __nv_bfloat16* srcb = buf ? Blo : Bhi;
                uint32_t sw = (uint32_t)r * 128
                            + (((uint32_t)k16 * 16) ^ ((uint32_t)(r & 7) * 16));
                cp_async16(sbase + B_NXT + (uint32_t)buf * 16384 + sw,
                           srcb + (size_t)(bcol + r) * HID + (c + 1) * KC + k16 * 8);
            }
            asm volatile("cp.async.commit_group;" ::: "memory");
        }

        // ---- compute chunk c: 4 k16 steps x 3 terms ----
#pragma unroll
        for (int kk = 0; kk < 4; kk++) {
            uint32_t af[4][4], bf[4][2];
            uint32_t ak = (uint32_t)kk * 32 + akoff;
            uint32_t bk = (uint32_t)kk * 32 + bkoff;

#pragma unroll
            for (int mt = 0; mt < 4; mt++) {
                uint32_t off = (uint32_t)(wm * 64 + mt * 16 + arow) * 128 + (ak ^ axor);
                ldmx4(af[mt], sbase + A_HI + off);
            }
#pragma unroll
            for (int p = 0; p < 2; p++) {
                uint32_t r4[4];
                uint32_t off = (uint32_t)(wn * 32 + p * 16 + brow) * 128 + (bk ^ bxor);
                ldmx4(r4, sbase + B_LO + off);
                bf[2 * p][0] = r4[0]; bf[2 * p][1] = r4[1];
                bf[2 * p + 1][0] = r4[2]; bf[2 * p + 1][1] = r4[3];
            }
#pragma unroll
            for (int mt = 0; mt < 4; mt++)
#pragma unroll
                for (int j = 0; j < 4; j++) mma16816(acc[mt][j], af[mt], bf[j]);

#pragma unroll
            for (int p = 0; p < 2; p++) {
                uint32_t r4[4];
                uint32_t off = (uint32_t)(wn * 32 + p * 16 + brow) * 128 + (bk ^ bxor);
                ldmx4(r4, sbase + B_HI + off);
                bf[2 * p][0] = r4[0]; bf[2 * p][1] = r4[1];
                bf[2 * p + 1][0] = r4[2]; bf[2 * p + 1][1] = r4[3];
            }
#pragma unroll
            for (int mt = 0; mt < 4; mt++)
#pragma unroll
                for (int j = 0; j < 4; j++) mma16816(acc[mt][j], af[mt], bf[j]);

#pragma unroll
            for (int mt = 0; mt < 4; mt++) {
                uint32_t off = (uint32_t)(wm * 64 + mt * 16 + arow) * 128 + (ak ^ axor);
                ldmx4(af[mt], sbase + A_LO + off);
            }
#pragma unroll
            for (int mt = 0; mt < 4; mt++)
#pragma unroll
                for (int j = 0; j < 4; j++) mma16816(acc[mt][j], af[mt], bf[j]);
        }

        // ---- restage A for next chunk (single A buffer) ----
        if (c + 1 < NCH) {
            __syncthreads();
#pragma unroll
            for (int i = 0; i < 8; i++) {
                int idx = tid + i * 256;
                int row = idx >> 4;
                int k4 = (idx & 15) * 4;
                int grow = block_row + row;
                float4 v = make_float4(0.f, 0.f, 0.f, 0.f);
                if (grow < xrows)
                    v = *(const float4*)(X + (size_t)grow * HID + (c + 1) * KC + k4);
                if (do_relu) {
                    v.x = fmaxf(v.x, 0.f); v.y = fmaxf(v.y, 0.f);
                    v.z = fmaxf(v.z, 0.f); v.w = fmaxf(v.w, 0.f);
                }
                __nv_bfloat162 h01 = __floats2bfloat162_rn(v.x, v.y);
                __nv_bfloat162 h23 = __floats2bfloat162_rn(v.z, v.w);
                __nv_bfloat162 l01 = __floats2bfloat162_rn(v.x - __bfloat162float(h01.x),
                                                           v.y - __bfloat162float(h01.y));
                __nv_bfloat162 l23 = __floats2bfloat162_rn(v.z - __bfloat162float(h23.x),
                                                           v.w - __bfloat162float(h23.y));
                uint32_t sw = (uint32_t)row * 128
                            + (((uint32_t)k4 * 2) ^ ((uint32_t)(row & 7) * 16));
                uint2 hv, lv;
                hv.x = *(const uint32_t*)&h01; hv.y = *(const uint32_t*)&h23;
                lv.x = *(const uint32_t*)&l01; lv.y = *(const uint32_t*)&l23;
                *(uint2*)(smem + A_HI + sw) = hv;
                *(uint2*)(smem + A_LO + sw) = lv;
            }
            asm volatile("cp.async.wait_group 0;" ::: "memory");
            __syncthreads();
        }
    }

    if (nt == 8) {
#pragma unroll
        for (int mt = 0; mt < 4; mt++) {
            int r0 = block_row + wm * 64 + mt * 16 + (lid >> 2);
#pragma unroll
            for (int j = 0; j < 4; j++) {
                int col = wn * 32 + j * 8 + (lid & 3) * 2;
                if (r0 < acc_rows) {
                    float* p = acc_out + (size_t)r0 * HID + col;
                    asm volatile("red.global.add.v2.f32 [%0], {%1, %2};"
                                 :: "l"(p), "f"(acc[mt][j][0]), "f"(acc[mt][j][1]) : "memory");
                }
                if (r0 + 8 < acc_rows) {
                    float* p = acc_out + (size_t)(r0 + 8) * HID + col;
                    asm volatile("red.global.add.v2.f32 [%0], {%1, %2};"
                                 :: "l"(p), "f"(acc[mt][j][2]), "f"(acc[mt][j][3]) : "memory");
                }
            }
        }
        return;
    }

    // relation tile: stage fp32 tile to smem (reuses first 64KB), scatter bucket edges
    __syncthreads();
#pragma unroll
    for (int mt = 0; mt < 4; mt++) {
        int r0 = wm * 64 + mt * 16 + (lid >> 2);
#pragma unroll
        for (int j = 0; j < 4; j++) {
            int col = wn * 32 + j * 8 + (lid & 3) * 2;
            *(float2*)(stile + r0 * 128 + col)       = make_float2(acc[mt][j][0], acc[mt][j][1]);
            *(float2*)(stile + (r0 + 8) * 128 + col) = make_float2(acc[mt][j][2], acc[mt][j][3]);
        }
    }
    __syncthreads();

    const int pn = min(ecnt, ECAP);
    for (int e = wid; e < pn; e += 8) {
        int4 ed = sedge[e];
        float sc = __int_as_float(ed.z);
        const float4 v = *(const float4*)(stile + (ed.x - block_row) * 128 + lid * 4);
        float4* p = (float4*)(acc_out + (size_t)ed.y * HID) + lid;
        asm volatile("red.global.add.v4.f32 [%0], {%1, %2, %3, %4};"
                     :: "l"(p), "f"(v.x * sc), "f"(v.y * sc), "f"(v.z * sc), "f"(v.w * sc)
                     : "memory");
    }
    for (int e = ECAP + wid; e < ecnt; e += 8) {
        int4 ed = edge[e0 + e];
        float sc = __int_as_float(ed.z);
        const float4 v = *(const float4*)(stile + (ed.x - block_row) * 128 + lid * 4);
        float4* p = (float4*)(acc_out + (size_t)ed.y * HID) + lid;
        asm volatile("red.global.add.v4.f32 [%0], {%1, %2, %3, %4};"
                     :: "l"(p), "f"(v.x * sc), "f"(v.y * sc), "f"(v.z * sc), "f"(v.w * sc)
                     : "memory");
    }
}

// ---------------- launch ----------------
extern "C" void kernel_launch(void* const* d_in, const int* in_sizes, int n_in,
                              void* d_out, int out_size) {
    const int* edge_index = (const int*)d_in[0];
    const int* edge_type  = (const int*)d_in[1];
    const float* node_emb = (const float*)d_in[2];
    const float* W1    = (const float*)d_in[3];
    const float* root1 = (const float*)d_in[4];
    const float* b1    = (const float*)d_in[5];
    const float* W2    = (const float*)d_in[6];
    const float* root2 = (const float*)d_in[7];
    const float* b2    = (const float*)d_in[8];
    float* out = (float*)d_out;

    const int E = in_sizes[0] / 2;
    const int* src = edge_index;
    const int* dst = edge_index + E;

    float *t, *cnt;
    __nv_bfloat16 *bhi1, *blo1, *bhi2, *blo2;
    int *hist, *cur, *boff;
    int4* edge;
    cudaGetSymbolAddress((void**)&t,    g_t);
    cudaGetSymbolAddress((void**)&cnt,  g_cnt);
    cudaGetSymbolAddress((void**)&bhi1, g_bhi1);
    cudaGetSymbolAddress((void**)&blo1, g_blo1);
    cudaGetSymbolAddress((void**)&bhi2, g_bhi2);
    cudaGetSymbolAddress((void**)&blo2, g_blo2);
    cudaGetSymbolAddress((void**)&hist, g_hist);
    cudaGetSymbolAddress((void**)&cur,  g_cur);
    cudaGetSymbolAddress((void**)&boff, g_boff);
    cudaGetSymbolAddress((void**)&edge, g_edge);

    const int T = 256;
    const dim3 gemm_grid(9, NMB);
    const int SMEM_BYTES = 98304 + ECAP * 16;   // 106496
    cudaFuncSetAttribute(gemm_fused, cudaFuncAttributeMaxDynamicSharedMemorySize, SMEM_BYTES);

    // ---- prep ----
    cudaMemsetAsync(cnt, 0, sizeof(float) * (size_t)NN * NREL, 0);
    cudaMemsetAsync(hist, 0, sizeof(int) * NB2, 0);
    cudaMemsetAsync(cur, 0, sizeof(int) * NB2, 0);
    counthist_kernel<<<(E + T * 4 - 1) / (T * 4), T>>>(src, dst, edge_type, E, cnt, hist);
    prep_kernel<<<2 * BCONV_BLKS + BINIT_T_BLKS + BINIT_O_BLKS, T>>>(
        W1, root1, W2, root2, b1, b2, bhi1, blo1, bhi2, blo2, t, out);
    scan_kernel<<<1, 1024>>>(hist, boff);
    reorder_kernel<<<(E + T * 2 - 1) / (T * 2), T>>>(src, dst, edge_type, E, boff, cur,
                                                     cnt, edge);

    // ---- layer 1: A = node_emb (no relu), accumulate into t ----
    gemm_fused<<<gemm_grid, T, SMEM_BYTES>>>(node_emb, NN, 0, bhi1, blo1,
                                             t, NPAD, edge, boff);
    // ---- layer 2: A = relu(t), accumulate into out ----
    gemm_fused<<<gemm_grid, T, SMEM_BYTES>>>(t, NPAD, 1, bhi2, blo2,
                                             out, NN, edge, boff);
}

// round 14
// speedup vs baseline: 1.1141x; 1.0093x over previous
#include <cuda_runtime.h>
#include <cuda_bf16.h>
#include <cstdint>

#define NN   50000
#define NPAD 50048              // 391 * 128
#define HID  128
#define NREL 8
#define KC   64
#define NCH  2                  // 128/64
#define NMB  391
#define NSUB 8
#define NB2  (NMB * NREL * NSUB)    // 25024 buckets
#define EMAX 600000
#define ECAP 512                // smem edge records per (block, rel)
#define ND   (NREL * HID + HID)

// ---------------- scratch ----------------
__device__ float g_t[(size_t)NPAD * HID];
__device__ float g_cnt[(size_t)NN * NREL];
__device__ __nv_bfloat16 g_bhi1[ND * HID];
__device__ __nv_bfloat16 g_blo1[ND * HID];
__device__ __nv_bfloat16 g_bhi2[ND * HID];
__device__ __nv_bfloat16 g_blo2[ND * HID];
__device__ int g_hist[NB2];
__device__ int g_cur[NB2];
__device__ int g_boff[NB2 + 1];
__device__ int4 g_edge[EMAX];    // (src, dst, scale_bits, 0), bucket-sorted

// ---------------- helpers ----------------
__device__ __forceinline__ void ldmx4(uint32_t* r, uint32_t addr) {
    asm volatile("ldmatrix.sync.aligned.m8n8.x4.shared.b16 {%0,%1,%2,%3}, [%4];"
                 : "=r"(r[0]), "=r"(r[1]), "=r"(r[2]), "=r"(r[3]) : "r"(addr));
}
__device__ __forceinline__ void mma16816(float* c, const uint32_t* a, const uint32_t* b) {
    asm volatile("mma.sync.aligned.m16n8k16.row.col.f32.bf16.bf16.f32 "
                 "{%0,%1,%2,%3}, {%4,%5,%6,%7}, {%8,%9}, {%0,%1,%2,%3};"
                 : "+f"(c[0]), "+f"(c[1]), "+f"(c[2]), "+f"(c[3])
                 : "r"(a[0]), "r"(a[1]), "r"(a[2]), "r"(a[3]), "r"(b[0]), "r"(b[1]));
}
__device__ __forceinline__ uint32_t smem_u32(const void* p) {
    uint32_t a;
    asm("{ .reg .u64 t; cvta.to.shared.u64 t, %1; cvt.u32.u64 %0, t; }" : "=r"(a) : "l"(p));
    return a;
}
__device__ __forceinline__ void cp_async16(uint32_t saddr, const void* gaddr) {
    asm volatile("cp.async.cg.shared.global [%0], [%1], 16;" :: "r"(saddr), "l"(gaddr));
}
__device__ __forceinline__ void red_add_f32(float* p, float v) {
    asm volatile("red.global.add.f32 [%0], %1;" :: "l"(p), "f"(v) : "memory");
}
__device__ __forceinline__ void red_add_s32(int* p, int v) {
    asm volatile("red.global.add.s32 [%0], %1;" :: "l"(p), "r"(v) : "memory");
}

// ---------------- small kernels ----------------
__global__ void counthist_kernel(const int* __restrict__ src, const int* __restrict__ dst,
                                 const int* __restrict__ rel, int E,
                                 float* __restrict__ cnt, int* __restrict__ hist) {
    int base = (blockIdx.x * blockDim.x + threadIdx.x) * 4;
#pragma unroll
    for (int i = 0; i < 4; i++) {
        int e = base + i;
        if (e < E) {
            int s = __ldg(src + e);
            int r = __ldg(rel + e);
            red_add_f32(&cnt[__ldg(dst + e) * NREL + r], 1.0f);
            red_add_s32(&hist[((s >> 7) * NREL + r) * NSUB + ((s >> 4) & 7)], 1);
        }
    }
}
#define VPT 25
__global__ void scan_kernel(const int* __restrict__ hist, int* __restrict__ boff) {
    __shared__ int part[1024];
    int t = threadIdx.x;
    int vals[VPT];
    int s = 0;
#pragma unroll
    for (int i = 0; i < VPT; i++) {
        int b = t * VPT + i;
        vals[i] = (b < NB2) ? hist[b] : 0;
        s += vals[i];
    }
    part[t] = s;
    __syncthreads();
    for (int off = 1; off < 1024; off <<= 1) {
        int v = (t >= off) ? part[t - off] : 0;
        __syncthreads();
        part[t] += v;
        __syncthreads();
    }
    int run = (t > 0) ? part[t - 1] : 0;
#pragma unroll
    for (int i = 0; i < VPT; i++) {
        int b = t * VPT + i;
        if (b <= NB2) boff[b] = run;
        run += vals[i];
    }
    if (t == 1023) boff[NB2] = run;
}

// merged: reorder (latency-bound, first) || bconv x2 + binit x2 (bandwidth-bound)
#define RBLK ((EMAX + 511) / 512)                 // 1172  (2 edges/thread)
#define BCONV_BLKS ((ND * HID + 255) / 256)       // 576
#define BINIT_T_BLKS ((NPAD * 32 + 255) / 256)    // 6256
#define BINIT_O_BLKS ((NN * 32 + 255) / 256)      // 6250
__global__ void prep_kernel(const int* __restrict__ src, const int* __restrict__ dst,
                            const int* __restrict__ rel, int E,
                            const int* __restrict__ boff, int* __restrict__ cur,
                            const float* __restrict__ cnt, int4* __restrict__ edge,
                            const float* __restrict__ W1, const float* __restrict__ root1,
                            const float* __restrict__ W2, const float* __restrict__ root2,
                            const float* __restrict__ b1, const float* __restrict__ b2,
                            __nv_bfloat16* __restrict__ bhi1, __nv_bfloat16* __restrict__ blo1,
                            __nv_bfloat16* __restrict__ bhi2, __nv_bfloat16* __restrict__ blo2,
                            float* __restrict__ t, float* __restrict__ out) {
    int bx = blockIdx.x;
    if (bx < RBLK) {
        // ---- reorder: 2 independent edges/thread ----
        int base = (bx * 256 + threadIdx.x) * 2;
        int s[2], d[2], r[2], pos[2];
        float sc[2];
        int n = min(2, E - base);
        if (n <= 0) return;
#pragma unroll
        for (int i = 0; i < 2; i++) {
            if (i < n) {
                s[i] = __ldg(src + base + i);
                d[i] = __ldg(dst + base + i);
                r[i] = __ldg(rel + base + i);
            }
        }
#pragma unroll
        for (int i = 0; i < 2; i++) {
            if (i < n) {
                int b = ((s[i] >> 7) * NREL + r[i]) * NSUB + ((s[i] >> 4) & 7);
                pos[i] = __ldg(boff + b) + atomicAdd(&cur[b], 1);
                sc[i] = 1.0f / fmaxf(__ldg(cnt + d[i] * NREL + r[i]), 1.0f);
            }
        }
#pragma unroll
        for (int i = 0; i < 2; i++)
            if (i < n) edge[pos[i]] = make_int4(s[i], d[i], __float_as_int(sc[i]), 0);
        return;
    }
    bx -= RBLK;
    if (bx < 2 * BCONV_BLKS) {
        int layer = bx >= BCONV_BLKS;
        const float* W = layer ? W2 : W1;
        const float* root = layer ? root2 : root1;
        __nv_bfloat16* bhi = layer ? bhi2 : bhi1;
        __nv_bfloat16* blo = layer ? blo2 : blo1;
        int i = (bx - layer * BCONV_BLKS) * 256 + threadIdx.x;
        if (i >= ND * HID) return;
        int nn = i >> 7, k = i & 127;
        float v = (nn < NREL * HID) ? W[((size_t)(nn >> 7) * HID + k) * HID + (nn & 127)]
                                    : root[(size_t)k * HID + (nn - NREL * HID)];
        __nv_bfloat16 h = __float2bfloat16(v);
        bhi[i] = h;
        blo[i] = __float2bfloat16(v - __bfloat162float(h));
        return;
    }
    bx -= 2 * BCONV_BLKS;
    if (bx < BINIT_T_BLKS) {
        int i = bx * 256 + threadIdx.x;
        if (i < NPAD * 32) ((float4*)t)[i] = ((const float4*)b1)[i & 31];
        return;
    }
    bx -= BINIT_T_BLKS;
    int i = bx * 256 + threadIdx.x;
    if (i < NN * 32) ((float4*)out)[i] = ((const float4*)b2)[i & 31];
}

// ---------------- fused bf16x3 GEMM (pipelined) + scatter ----------------
// smem 104KB: A_HI 16K @0, A_LO 16K @16K, B buf0 32K @32K, B buf1 32K @64K, edges 8K @96K.
__global__ void __launch_bounds__(256, 2)
gemm_fused(const float* __restrict__ X, int xrows, int do_relu,
           const __nv_bfloat16* __restrict__ Bhi, const __nv_bfloat16* __restrict__ Blo,
           float* __restrict__ acc_out, int acc_rows,
           const int4* __restrict__ edge, const int* __restrict__ boff) {
    extern __shared__ char smem[];
    const uint32_t sbase = smem_u32(smem);
    const uint32_t A_HI = 0, A_LO = 16384, B_BUF0 = 32768, EDG = 98304;
    float* stile = (float*)smem;
    const int4* sedge = (const int4*)(smem + EDG);

    const int tid = threadIdx.x, wid = tid >> 5, lid = tid & 31;
    const int nt = blockIdx.x;                 // 0..7 relations, 8 root
    const int block_row = blockIdx.y * 128;
    const int bcol = nt * 128;
    const int wm = wid >> 2, wn = wid & 3;

    // ---- edge prefetch (relation tiles only) ----
    int e0 = 0, ecnt = 0;
    if (nt < 8) {
        const int b8 = (blockIdx.y * NREL + nt) * NSUB;
        e0 = boff[b8];
        ecnt = boff[b8 + NSUB] - e0;
        int pn = min(ecnt, ECAP);
        for (int i = tid; i < pn; i += 256)
            cp_async16(sbase + EDG + i * 16, edge + e0 + i);
    }

    // ---- B chunk0 -> buf0 via cp.async ----
#pragma unroll
    for (int i = 0; i < 8; i++) {
        int idx = tid + i * 256;
        int buf = idx >> 10;
        int r = (idx >> 3) & 127;
        int k16 = idx & 7;
        const __nv_bfloat16* srcb = buf ? Blo : Bhi;
        uint32_t sw = (uint32_t)r * 128 + (((uint32_t)k16 * 16) ^ ((uint32_t)(r & 7) * 16));
        cp_async16(sbase + B_BUF0 + (uint32_t)buf * 16384 + sw,
                   srcb + (size_t)(bcol + r) * HID + k16 * 8);
    }
    asm volatile("cp.async.commit_group;" ::: "memory");

    const int arow = (lid & 15);
    const uint32_t akoff = (uint32_t)(lid >> 4) * 16;
    const uint32_t axor = (uint32_t)(arow & 7) * 16;
    const int brow = (lid & 7) + ((lid >> 4) * 8);
    const uint32_t bkoff = (uint32_t)((lid >> 3) & 1) * 16;
    const uint32_t bxor = (uint32_t)(brow & 7) * 16;

    float acc[4][4][4];
#pragma unroll
    for (int i = 0; i < 4; i++)
#pragma unroll
        for (int j = 0; j < 4; j++)
#pragma unroll
            for (int v = 0; v < 4; v++) acc[i][j][v] = 0.0f;

    // ---- stage A chunk0 ----
#pragma unroll
    for (int i = 0; i < 8; i++) {
        int idx = tid + i * 256;
        int row = idx >> 4;
        int k4 = (idx & 15) * 4;
        int grow = block_row + row;
        float4 v = make_float4(0.f, 0.f, 0.f, 0.f);
        if (grow < xrows) v = *(const float4*)(X + (size_t)grow * HID + k4);
        if (do_relu) {
            v.x = fmaxf(v.x, 0.f); v.y = fmaxf(v.y, 0.f);
            v.z = fmaxf(v.z, 0.f); v.w = fmaxf(v.w, 0.f);
        }
        __nv_bfloat162 h01 = __floats2bfloat162_rn(v.x, v.y);
        __nv_bfloat162 h23 = __floats2bfloat162_rn(v.z, v.w);
        __nv_bfloat162 l01 = __floats2bfloat162_rn(v.x - __bfloat162float(h01.x),
                                                   v.y - __bfloat162float(h01.y));
        __nv_bfloat162 l23 = __floats2bfloat162_rn(v.z - __bfloat162float(h23.x),
                                                   v.w - __bfloat162float(h23.y));
        uint32_t sw = (uint32_t)row * 128 + (((uint32_t)k4 * 2) ^ ((uint32_t)(row & 7) * 16));
        uint2 hv, lv;
        hv.x = *(const uint32_t*)&h01; hv.y = *(const uint32_t*)&h23;
        lv.x = *(const uint32_t*)&l01; lv.y = *(const uint32_t*)&l23;
        *(uint2*)(smem + A_HI + sw) = hv;
        *(uint2*)(smem + A_LO + sw) = lv;
    }
    asm volatile("cp.async.wait_group 0;" ::: "memory");
    __syncthreads();

    for (int c = 0; c < NCH; c++) {
        const uint32_t B_HI = B_BUF0 + (uint32_t)(c & 1) * 32768;
        const uint32_t B_LO = B_HI + 16384;

        if (c + 1 < NCH) {
            const uint32_t B_NXT = B_BUF0 + (uint32_t)((c + 1) & 1) * 32768;
#pragma unroll
            for (int i = 0; i < 8; i++) {
                int idx = tid + i * 256;
                int buf = idx >> 10;
                int r = (idx >> 3) & 127;
                int k16 = idx & 7;
                const __nv_bfloat16* srcb = buf ? Blo : Bhi;
                uint32_t sw = (uint32_t)r * 128
                            + (((uint32_t)k16 * 16) ^ ((uint32_t)(r & 7) * 16));
                cp_async16(sbase + B_NXT + (uint32_t)buf * 16384 + sw,
                           srcb + (size_t)(bcol + r) * HID + (c + 1) * KC + k16 * 8);
            }
            asm volatile("cp.async.commit_group;" ::: "memory");
        }

#pragma unroll
        for (int kk = 0; kk < 4; kk++) {
            uint32_t af[4][4], bf[4][2];
            uint32_t ak = (uint32_t)kk * 32 + akoff;
            uint32_t bk = (uint32_t)kk * 32 + bkoff;

#pragma unroll
            for (int mt = 0; mt < 4; mt++) {
                uint32_t off = (uint32_t)(wm * 64 + mt * 16 + arow) * 128 + (ak ^ axor);
                ldmx4(af[mt], sbase + A_HI + off);
            }
#pragma unroll
            for (int p = 0; p < 2; p++) {
                uint32_t r4[4];
                uint32_t off = (uint32_t)(wn * 32 + p * 16 + brow) * 128 + (bk ^ bxor);
                ldmx4(r4, sbase + B_LO + off);
                bf[2 * p][0] = r4[0]; bf[2 * p][1] = r4[1];
                bf[2 * p + 1][0] = r4[2]; bf[2 * p + 1][1] = r4[3];
            }
#pragma unroll
            for (int mt = 0; mt < 4; mt++)
#pragma unroll
                for (int j = 0; j < 4; j++) mma16816(acc[mt][j], af[mt], bf[j]);

#pragma unroll
            for (int p = 0; p < 2; p++) {
                uint32_t r4[4];
                uint32_t off = (uint32_t)(wn * 32 + p * 16 + brow) * 128 + (bk ^ bxor);
                ldmx4(r4, sbase + B_HI + off);
                bf[2 * p][0] = r4[0]; bf[2 * p][1] = r4[1];
                bf[2 * p + 1][0] = r4[2]; bf[2 * p + 1][1] = r4[3];
            }
#pragma unroll
            for (int mt = 0; mt < 4; mt++)
#pragma unroll
                for (int j = 0; j < 4; j++) mma16816(acc[mt][j], af[mt], bf[j]);

#pragma unroll
            for (int mt = 0; mt < 4; mt++) {
                uint32_t off = (uint32_t)(wm * 64 + mt * 16 + arow) * 128 + (ak ^ axor);
                ldmx4(af[mt], sbase + A_LO + off);
            }
#pragma unroll
            for (int mt = 0; mt < 4; mt++)
#pragma unroll
                for (int j = 0; j < 4; j++) mma16816(acc[mt][j], af[mt], bf[j]);
        }

        if (c + 1 < NCH) {
            __syncthreads();
#pragma unroll
            for (int i = 0; i < 8; i++) {
                int idx = tid + i * 256;
                int row = idx >> 4;
                int k4 = (idx & 15) * 4;
                int grow = block_row + row;
                float4 v = make_float4(0.f, 0.f, 0.f, 0.f);
                if (grow < xrows)
                    v = *(const float4*)(X + (size_t)grow * HID + (c + 1) * KC + k4);
                if (do_relu) {
                    v.x = fmaxf(v.x, 0.f); v.y = fmaxf(v.y, 0.f);
                    v.z = fmaxf(v.z, 0.f); v.w = fmaxf(v.w, 0.f);
                }
                __nv_bfloat162 h01 = __floats2bfloat162_rn(v.x, v.y);
                __nv_bfloat162 h23 = __floats2bfloat162_rn(v.z, v.w);
                __nv_bfloat162 l01 = __floats2bfloat162_rn(v.x - __bfloat162float(h01.x),
                                                           v.y - __bfloat162float(h01.y));
                __nv_bfloat162 l23 = __floats2bfloat162_rn(v.z - __bfloat162float(h23.x),
                                                           v.w - __bfloat162float(h23.y));
                uint32_t sw = (uint32_t)row * 128
                            + (((uint32_t)k4 * 2) ^ ((uint32_t)(row & 7) * 16));
                uint2 hv, lv;
                hv.x = *(const uint32_t*)&h01; hv.y = *(const uint32_t*)&h23;
                lv.x = *(const uint32_t*)&l01; lv.y = *(const uint32_t*)&l23;
                *(uint2*)(smem + A_HI + sw) = hv;
                *(uint2*)(smem + A_LO + sw) = lv;
            }
            asm volatile("cp.async.wait_group 0;" ::: "memory");
            __syncthreads();
        }
    }

    if (nt == 8) {
#pragma unroll
        for (int mt = 0; mt < 4; mt++) {
            int r0 = block_row + wm * 64 + mt * 16 + (lid >> 2);
#pragma unroll
            for (int j = 0; j < 4; j++) {
                int col = wn * 32 + j * 8 + (lid & 3) * 2;
                if (r0 < acc_rows) {
                    float* p = acc_out + (size_t)r0 * HID + col;
                    asm volatile("red.global.add.v2.f32 [%0], {%1, %2};"
                                 :: "l"(p), "f"(acc[mt][j][0]), "f"(acc[mt][j][1]) : "memory");
                }
                if (r0 + 8 < acc_rows) {
                    float* p = acc_out + (size_t)(r0 + 8) * HID + col;
                    asm volatile("red.global.add.v2.f32 [%0], {%1, %2};"
                                 :: "l"(p), "f"(acc[mt][j][2]), "f"(acc[mt][j][3]) : "memory");
                }
            }
        }
        return;
    }

    __syncthreads();
#pragma unroll
    for (int mt = 0; mt < 4; mt++) {
        int r0 = wm * 64 + mt * 16 + (lid >> 2);
#pragma unroll
        for (int j = 0; j < 4; j++) {
            int col = wn * 32 + j * 8 + (lid & 3) * 2;
            *(float2*)(stile + r0 * 128 + col)       = make_float2(acc[mt][j][0], acc[mt][j][1]);
            *(float2*)(stile + (r0 + 8) * 128 + col) = make_float2(acc[mt][j][2], acc[mt][j][3]);
        }
    }
    __syncthreads();

    const int pn = min(ecnt, ECAP);
    for (int e = wid; e < pn; e += 8) {
        int4 ed = sedge[e];
        float sc = __int_as_float(ed.z);
        const float4 v = *(const float4*)(stile + (ed.x - block_row) * 128 + lid * 4);
        float4* p = (float4*)(acc_out + (size_t)ed.y * HID) + lid;
        asm volatile("red.global.add.v4.f32 [%0], {%1, %2, %3, %4};"
                     :: "l"(p), "f"(v.x * sc), "f"(v.y * sc), "f"(v.z * sc), "f"(v.w * sc)
                     : "memory");
    }
    for (int e = ECAP + wid; e < ecnt; e += 8) {
        int4 ed = edge[e0 + e];
        float sc = __int_as_float(ed.z);
        const float4 v = *(const float4*)(stile + (ed.x - block_row) * 128 + lid * 4);
        float4* p = (float4*)(acc_out + (size_t)ed.y * HID) + lid;
        asm volatile("red.global.add.v4.f32 [%0], {%1, %2, %3, %4};"
                     :: "l"(p), "f"(v.x * sc), "f"(v.y * sc), "f"(v.z * sc), "f"(v.w * sc)
                     : "memory");
    }
}

// ---------------- launch ----------------
extern "C" void kernel_launch(void* const* d_in, const int* in_sizes, int n_in,
                              void* d_out, int out_size) {
    const int* edge_index = (const int*)d_in[0];
    const int* edge_type  = (const int*)d_in[1];
    const float* node_emb = (const float*)d_in[2];
    const float* W1    = (const float*)d_in[3];
    const float* root1 = (const float*)d_in[4];
    const float* b1    = (const float*)d_in[5];
    const float* W2    = (const float*)d_in[6];
    const float* root2 = (const float*)d_in[7];
    const float* b2    = (const float*)d_in[8];
    float* out = (float*)d_out;

    const int E = in_sizes[0] / 2;
    const int* src = edge_index;
    const int* dst = edge_index + E;

    float *t, *cnt;
    __nv_bfloat16 *bhi1, *blo1, *bhi2, *blo2;
    int *hist, *cur, *boff;
    int4* edge;
    cudaGetSymbolAddress((void**)&t,    g_t);
    cudaGetSymbolAddress((void**)&cnt,  g_cnt);
    cudaGetSymbolAddress((void**)&bhi1, g_bhi1);
    cudaGetSymbolAddress((void**)&blo1, g_blo1);
    cudaGetSymbolAddress((void**)&bhi2, g_bhi2);
    cudaGetSymbolAddress((void**)&blo2, g_blo2);
    cudaGetSymbolAddress((void**)&hist, g_hist);
    cudaGetSymbolAddress((void**)&cur,  g_cur);
    cudaGetSymbolAddress((void**)&boff, g_boff);
    cudaGetSymbolAddress((void**)&edge, g_edge);

    const int T = 256;
    const dim3 gemm_grid(9, NMB);
    const int SMEM_BYTES = 98304 + ECAP * 16;   // 106496
    cudaFuncSetAttribute(gemm_fused, cudaFuncAttributeMaxDynamicSharedMemorySize, SMEM_BYTES);

    // ---- prep ----
    cudaMemsetAsync(cnt, 0, sizeof(float) * (size_t)NN * NREL, 0);
    cudaMemsetAsync(hist, 0, sizeof(int) * NB2, 0);
    cudaMemsetAsync(cur, 0, sizeof(int) * NB2, 0);
    counthist_kernel<<<(E + T * 4 - 1) / (T * 4), T>>>(src, dst, edge_type, E, cnt, hist);
    scan_kernel<<<1, 1024>>>(hist, boff);
    prep_kernel<<<RBLK + 2 * BCONV_BLKS + BINIT_T_BLKS + BINIT_O_BLKS, T>>>(
        src, dst, edge_type, E, boff, cur, cnt, edge,
        W1, root1, W2, root2, b1, b2, bhi1, blo1, bhi2, blo2, t, out);

    // ---- layer 1: A = node_emb (no relu), accumulate into t ----
    gemm_fused<<<gemm_grid, T, SMEM_BYTES>>>(node_emb, NN, 0, bhi1, blo1,
                                             t, NPAD, edge, boff);
    // ---- layer 2: A = relu(t), accumulate into out ----
    gemm_fused<<<gemm_grid, T, SMEM_BYTES>>>(t, NPAD, 1, bhi2, blo2,
                                             out, NN, edge, boff);
}

// round 15
// speedup vs baseline: 1.1723x; 1.0522x over previous
#include <cuda_runtime.h>
#include <cuda_bf16.h>
#include <cstdint>

#define NN   50000
#define NPAD 50048              // 391 * 128
#define HID  128
#define NREL 8
#define KC   32
#define NCH  4                  // 128/32
#define NMB  391
#define NSUB 8
#define NB2  (NMB * NREL * NSUB)    // 25024 buckets
#define EMAX 600000
#define ECAP 512
#define ND   (NREL * HID + HID)
#define STG  32768              // stage size: A_HI 8K | A_LO 8K | B_HI 8K | B_LO 8K

// ---------------- scratch ----------------
__device__ float g_t[(size_t)NPAD * HID];
__device__ float g_cnt[(size_t)NN * NREL];
__device__ __nv_bfloat16 g_xhi[(size_t)NPAD * HID];
__device__ __nv_bfloat16 g_xlo[(size_t)NPAD * HID];
__device__ __nv_bfloat16 g_bhi1[ND * HID];
__device__ __nv_bfloat16 g_blo1[ND * HID];
__device__ __nv_bfloat16 g_bhi2[ND * HID];
__device__ __nv_bfloat16 g_blo2[ND * HID];
__device__ int g_hist[NB2];
__device__ int g_cur[NB2];
__device__ int g_boff[NB2 + 1];
__device__ int4 g_edge[EMAX];

// ---------------- helpers ----------------
__device__ __forceinline__ void ldmx4(uint32_t* r, uint32_t addr) {
    asm volatile("ldmatrix.sync.aligned.m8n8.x4.shared.b16 {%0,%1,%2,%3}, [%4];"
                 : "=r"(r[0]), "=r"(r[1]), "=r"(r[2]), "=r"(r[3]) : "r"(addr));
}
__device__ __forceinline__ void mma16816(float* c, const uint32_t* a, const uint32_t* b) {
    asm volatile("mma.sync.aligned.m16n8k16.row.col.f32.bf16.bf16.f32 "
                 "{%0,%1,%2,%3}, {%4,%5,%6,%7}, {%8,%9}, {%0,%1,%2,%3};"
                 : "+f"(c[0]), "+f"(c[1]), "+f"(c[2]), "+f"(c[3])
                 : "r"(a[0]), "r"(a[1]), "r"(a[2]), "r"(a[3]), "r"(b[0]), "r"(b[1]));
}
__device__ __forceinline__ uint32_t smem_u32(const void* p) {
    uint32_t a;
    asm("{ .reg .u64 t; cvta.to.shared.u64 t, %1; cvt.u32.u64 %0, t; }" : "=r"(a) : "l"(p));
    return a;
}
__device__ __forceinline__ void cp_async16(uint32_t saddr, const void* gaddr) {
    asm volatile("cp.async.cg.shared.global [%0], [%1], 16;" :: "r"(saddr), "l"(gaddr));
}
template <int N> __device__ __forceinline__ void cpwait() {
    asm volatile("cp.async.wait_group %0;" :: "n"(N) : "memory");
}
__device__ __forceinline__ void cpcommit() {
    asm volatile("cp.async.commit_group;" ::: "memory");
}
__device__ __forceinline__ void red_add_f32(float* p, float v) {
    asm volatile("red.global.add.f32 [%0], %1;" :: "l"(p), "f"(v) : "memory");
}
__device__ __forceinline__ void red_add_s32(int* p, int v) {
    asm volatile("red.global.add.s32 [%0], %1;" :: "l"(p), "r"(v) : "memory");
}
// fp32 float4 -> bf16x2 hi/lo split (+optional relu), write to [row][128] arrays
__device__ __forceinline__ void xsplit_piece(int i, const float* __restrict__ src, int srows,
                                             int do_relu, __nv_bfloat16* __restrict__ hi,
                                             __nv_bfloat16* __restrict__ lo) {
    int row = i >> 5;
    float4 v = make_float4(0.f, 0.f, 0.f, 0.f);
    if (row < srows) v = ((const float4*)src)[i];
    if (do_relu) {
        v.x = fmaxf(v.x, 0.f); v.y = fmaxf(v.y, 0.f);
        v.z = fmaxf(v.z, 0.f); v.w = fmaxf(v.w, 0.f);
    }
    __nv_bfloat162 h01 = __floats2bfloat162_rn(v.x, v.y);
    __nv_bfloat162 h23 = __floats2bfloat162_rn(v.z, v.w);
    __nv_bfloat162 l01 = __floats2bfloat162_rn(v.x - __bfloat162float(h01.x),
                                               v.y - __bfloat162float(h01.y));
    __nv_bfloat162 l23 = __floats2bfloat162_rn(v.z - __bfloat162float(h23.x),
                                               v.w - __bfloat162float(h23.y));
    uint2 hv, lv;
    hv.x = *(const uint32_t*)&h01; hv.y = *(const uint32_t*)&h23;
    lv.x = *(const uint32_t*)&l01; lv.y = *(const uint32_t*)&l23;
    ((uint2*)hi)[i] = hv;
    ((uint2*)lo)[i] = lv;
}

// ---------------- small kernels ----------------
__global__ void counthist_kernel(const int* __restrict__ src, const int* __restrict__ dst,
                                 const int* __restrict__ rel, int E,
                                 float* __restrict__ cnt, int* __restrict__ hist) {
    int base = (blockIdx.x * blockDim.x + threadIdx.x) * 4;
#pragma unroll
    for (int i = 0; i < 4; i++) {
        int e = base + i;
        if (e < E) {
            int s = __ldg(src + e);
            int r = __ldg(rel + e);
            red_add_f32(&cnt[__ldg(dst + e) * NREL + r], 1.0f);
            red_add_s32(&hist[((s >> 7) * NREL + r) * NSUB + ((s >> 4) & 7)], 1);
        }
    }
}
#define VPT 25
__global__ void scan_kernel(const int* __restrict__ hist, int* __restrict__ boff) {
    __shared__ int part[1024];
    int t = threadIdx.x;
    int vals[VPT];
    int s = 0;
#pragma unroll
    for (int i = 0; i < VPT; i++) {
        int b = t * VPT + i;
        vals[i] = (b < NB2) ? hist[b] : 0;
        s += vals[i];
    }
    part[t] = s;
    __syncthreads();
    for (int off = 1; off < 1024; off <<= 1) {
        int v = (t >= off) ? part[t - off] : 0;
        __syncthreads();
        part[t] += v;
        __syncthreads();
    }
    int run = (t > 0) ? part[t - 1] : 0;
#pragma unroll
    for (int i = 0; i < VPT; i++) {
        int b = t * VPT + i;
        if (b <= NB2) boff[b] = run;
        run += vals[i];
    }
    if (t == 1023) boff[NB2] = run;
}

// merged: reorder || bconv x2 || binit x2 || xsplit(layer1)
#define RBLK ((EMAX + 511) / 512)
#define BCONV_BLKS ((ND * HID + 255) / 256)
#define BINIT_T_BLKS ((NPAD * 32 + 255) / 256)
#define BINIT_O_BLKS ((NN * 32 + 255) / 256)
#define XS_BLKS ((NPAD * 32 + 255) / 256)
__global__ void prep_kernel(const int* __restrict__ src, const int* __restrict__ dst,
                            const int* __restrict__ rel, int E,
                            const int* __restrict__ boff, int* __restrict__ cur,
                            const float* __restrict__ cnt, int4* __restrict__ edge,
                            const float* __restrict__ W1, const float* __restrict__ root1,
                            const float* __restrict__ W2, const float* __restrict__ root2,
                            const float* __restrict__ b1, const float* __restrict__ b2,
                            __nv_bfloat16* __restrict__ bhi1, __nv_bfloat16* __restrict__ blo1,
                            __nv_bfloat16* __restrict__ bhi2, __nv_bfloat16* __restrict__ blo2,
                            float* __restrict__ t, float* __restrict__ out,
                            const float* __restrict__ x0,
                            __nv_bfloat16* __restrict__ xhi, __nv_bfloat16* __restrict__ xlo) {
    int bx = blockIdx.x;
    if (bx < RBLK) {
        int base = (bx * 256 + threadIdx.x) * 2;
        int s[2], d[2], r[2], pos[2];
        float sc[2];
        int n = min(2, E - base);
        if (n <= 0) return;
#pragma unroll
        for (int i = 0; i < 2; i++) {
            if (i < n) {
                s[i] = __ldg(src + base + i);
                d[i] = __ldg(dst + base + i);
                r[i] = __ldg(rel + base + i);
            }
        }
#pragma unroll
        for (int i = 0; i < 2; i++) {
            if (i < n) {
                int b = ((s[i] >> 7) * NREL + r[i]) * NSUB + ((s[i] >> 4) & 7);
                pos[i] = __ldg(boff + b) + atomicAdd(&cur[b], 1);
                sc[i] = 1.0f / fmaxf(__ldg(cnt + d[i] * NREL + r[i]), 1.0f);
            }
        }
#pragma unroll
        for (int i = 0; i < 2; i++)
            if (i < n) edge[pos[i]] = make_int4(s[i], d[i], __float_as_int(sc[i]), 0);
        return;
    }
    bx -= RBLK;
    if (bx < 2 * BCONV_BLKS) {
        int layer = bx >= BCONV_BLKS;
        const float* W = layer ? W2 : W1;
        const float* root = layer ? root2 : root1;
        __nv_bfloat16* bhi = layer ? bhi2 : bhi1;
        __nv_bfloat16* blo = layer ? blo2 : blo1;
        int i = (bx - layer * BCONV_BLKS) * 256 + threadIdx.x;
        if (i >= ND * HID) return;
        int nn = i >> 7, k = i & 127;
        float v = (nn < NREL * HID) ? W[((size_t)(nn >> 7) * HID + k) * HID + (nn & 127)]
                                    : root[(size_t)k * HID + (nn - NREL * HID)];
        __nv_bfloat16 h = __float2bfloat16(v);
        bhi[i] = h;
        blo[i] = __float2bfloat16(v - __bfloat162float(h));
        return;
    }
    bx -= 2 * BCONV_BLKS;
    if (bx < BINIT_T_BLKS) {
        int i = bx * 256 + threadIdx.x;
        if (i < NPAD * 32) ((float4*)t)[i] = ((const float4*)b1)[i & 31];
        return;
    }
    bx -= BINIT_T_BLKS;
    if (bx < BINIT_O_BLKS) {
        int i = bx * 256 + threadIdx.x;
        if (i < NN * 32) ((float4*)out)[i] = ((const float4*)b2)[i & 31];
        return;
    }
    bx -= BINIT_O_BLKS;
    int i = bx * 256 + threadIdx.x;
    if (i < NPAD * 32) xsplit_piece(i, x0, NN, 0, xhi, xlo);
}

// layer-2 A split: relu(t) -> xhi/xlo
__global__ void xsplit2_kernel(const float* __restrict__ t,
                               __nv_bfloat16* __restrict__ xhi, __nv_bfloat16* __restrict__ xlo) {
    int i = blockIdx.x * blockDim.x + threadIdx.x;
    if (i < NPAD * 32) xsplit_piece(i, t, NN, 1, xhi, xlo);
}

// ---------------- fused bf16x3 GEMM (3-stage cp.async pipeline) + scatter ----------------
// smem: 3 stages x 32KB @0, edges 8KB @98304. stile (64KB) reuses stages 0-1.
// Packed-pair swizzle for 128r x 32k bf16 tiles (64B rows, 2 rows per 128B line):
//   addr(row, kb) = (row>>1)*128 + (((row&1)*64 + kb) ^ (((row>>1)&7)*16))
__global__ void __launch_bounds__(256, 2)
gemm_fused(const __nv_bfloat16* __restrict__ Ahi, const __nv_bfloat16* __restrict__ Alo,
           const __nv_bfloat16* __restrict__ Bhi, const __nv_bfloat16* __restrict__ Blo,
           float* __restrict__ acc_out, int acc_rows,
           const int4* __restrict__ edge, const int* __restrict__ boff) {
    extern __shared__ char smem[];
    const uint32_t sbase = smem_u32(smem);
    const uint32_t EDG = 3 * STG;
    float* stile = (float*)smem;
    const int4* sedge = (const int4*)(smem + EDG);

    const int tid = threadIdx.x, wid = tid >> 5, lid = tid & 31;
    const int nt = blockIdx.x;                 // 0..7 relations, 8 root
    const int block_row = blockIdx.y * 128;
    const int bcol = nt * 128;
    const int wm = wid >> 2, wn = wid & 3;

    // issues one chunk's A/B hi+lo (2048 x 16B) into a stage
    auto issue_chunk = [&](uint32_t stg, int c) {
#pragma unroll
        for (int i = 0; i < 8; i++) {
            int idx = tid + i * 256;            // 0..2047
            int half = idx >> 10;               // 0 = A, 1 = B
            int q = idx & 1023;
            int comp = q >> 9;                  // 0 hi, 1 lo
            int r = (q >> 2) & 127;
            int j = q & 3;                      // 16B piece within 64B row
            const __nv_bfloat16* srcp;
            if (half == 0) srcp = (comp ? Alo : Ahi) + (size_t)(block_row + r) * HID + c * KC + j * 8;
            else           srcp = (comp ? Blo : Bhi) + (size_t)(bcol + r) * HID + c * KC + j * 8;
            uint32_t kb = (uint32_t)j * 16;
            uint32_t a = (uint32_t)(r >> 1) * 128
                       + ((((uint32_t)(r & 1)) * 64 + kb) ^ (((uint32_t)(r >> 1) & 7) * 16));
            uint32_t base = (half ? 16384u : 0u) + (comp ? 8192u : 0u);
            cp_async16(stg + base + a, srcp);
        }
    };

    // ---- prologue: edges + chunks 0..2 ----
    int e0 = 0, ecnt = 0;
    if (nt < 8) {
        const int b8 = (blockIdx.y * NREL + nt) * NSUB;
        e0 = boff[b8];
        ecnt = boff[b8 + NSUB] - e0;
        int pn = min(ecnt, ECAP);
        for (int i = tid; i < pn; i += 256)
            cp_async16(sbase + EDG + i * 16, edge + e0 + i);
    }
    issue_chunk(sbase + 0 * STG, 0); cpcommit();
    issue_chunk(sbase + 1 * STG, 1); cpcommit();
    issue_chunk(sbase + 2 * STG, 2); cpcommit();

    // per-lane fragment geometry
    const int arow = lid & 15;
    const uint32_t akoff = (uint32_t)(lid >> 4) * 16;
    const uint32_t asel = (uint32_t)(arow & 1) * 64;
    const uint32_t axorn = (uint32_t)((arow >> 1) & 7) * 16;
    const uint32_t abase = (uint32_t)(wm * 32 + (arow >> 1)) * 128;
    const int brow = (lid & 7) + ((lid >> 4) * 8);
    const uint32_t bkoff = (uint32_t)((lid >> 3) & 1) * 16;
    const uint32_t bsel = (uint32_t)(brow & 1) * 64;
    const uint32_t bxorn = (uint32_t)((brow >> 1) & 7) * 16;
    const uint32_t bbase = (uint32_t)(wn * 16 + (brow >> 1)) * 128;

    float acc[4][4][4];
#pragma unroll
    for (int i = 0; i < 4; i++)
#pragma unroll
        for (int j = 0; j < 4; j++)
#pragma unroll
            for (int v = 0; v < 4; v++) acc[i][j][v] = 0.0f;

    auto compute_chunk = [&](uint32_t stg) {
#pragma unroll
        for (int kk = 0; kk < 2; kk++) {
            uint32_t af[4][4], bf[4][2];
            uint32_t ka = (uint32_t)kk * 32 + akoff;    // 0..48
            uint32_t kb = (uint32_t)kk * 32 + bkoff;

#pragma unroll
            for (int mt = 0; mt < 4; mt++)
                ldmx4(af[mt], stg + abase + (uint32_t)mt * 1024 + ((asel + ka) ^ axorn));
#pragma unroll
            for (int p = 0; p < 2; p++) {
                uint32_t r4[4];
                ldmx4(r4, stg + 24576u + bbase + (uint32_t)p * 1024 + ((bsel + kb) ^ bxorn));
                bf[2 * p][0] = r4[0]; bf[2 * p][1] = r4[1];
                bf[2 * p + 1][0] = r4[2]; bf[2 * p + 1][1] = r4[3];
            }
#pragma unroll
            for (int mt = 0; mt < 4; mt++)
#pragma unroll
                for (int j = 0; j < 4; j++) mma16816(acc[mt][j], af[mt], bf[j]);

#pragma unroll
            for (int p = 0; p < 2; p++) {
                uint32_t r4[4];
                ldmx4(r4, stg + 16384u + bbase + (uint32_t)p * 1024 + ((bsel + kb) ^ bxorn));
                bf[2 * p][0] = r4[0]; bf[2 * p][1] = r4[1];
                bf[2 * p + 1][0] = r4[2]; bf[2 * p + 1][1] = r4[3];
            }
#pragma unroll
            for (int mt = 0; mt < 4; mt++)
#pragma unroll
                for (int j = 0; j < 4; j++) mma16816(acc[mt][j], af[mt], bf[j]);

#pragma unroll
            for (int mt = 0; mt < 4; mt++)
                ldmx4(af[mt], stg + 8192u + abase + (uint32_t)mt * 1024 + ((asel + ka) ^ axorn));
#pragma unroll
            for (int mt = 0; mt < 4; mt++)
#pragma unroll
                for (int j = 0; j < 4; j++) mma16816(acc[mt][j], af[mt], bf[j]);
        }
    };

    // ---- pipelined mainloop: chunks 0..3 over stages mod 3 ----
    cpwait<2>(); __syncthreads();
    compute_chunk(sbase + 0 * STG);
    __syncthreads();                       // all warps done with stage 0
    issue_chunk(sbase + 0 * STG, 3); cpcommit();
    cpwait<2>(); __syncthreads();
    compute_chunk(sbase + 1 * STG);
    cpwait<1>(); __syncthreads();
    compute_chunk(sbase + 2 * STG);
    cpwait<0>(); __syncthreads();
    compute_chunk(sbase + 0 * STG);

    if (nt == 8) {
#pragma unroll
        for (int mt = 0; mt < 4; mt++) {
            int r0 = block_row + wm * 64 + mt * 16 + (lid >> 2);
#pragma unroll
            for (int j = 0; j < 4; j++) {
                int col = wn * 32 + j * 8 + (lid & 3) * 2;
                if (r0 < acc_rows) {
                    float* p = acc_out + (size_t)r0 * HID + col;
                    asm volatile("red.global.add.v2.f32 [%0], {%1, %2};"
                                 :: "l"(p), "f"(acc[mt][j][0]), "f"(acc[mt][j][1]) : "memory");
                }
                if (r0 + 8 < acc_rows) {
                    float* p = acc_out + (size_t)(r0 + 8) * HID + col;
                    asm volatile("red.global.add.v2.f32 [%0], {%1, %2};"
                                 :: "l"(p), "f"(acc[mt][j][2]), "f"(acc[mt][j][3]) : "memory");
                }
            }
        }
        return;
    }

    // relation tile: stage fp32 tile to smem (stages 0-1), scatter bucket edges
    __syncthreads();
#pragma unroll
    for (int mt = 0; mt < 4; mt++) {
        int r0 = wm * 64 + mt * 16 + (lid >> 2);
#pragma unroll
        for (int j = 0; j < 4; j++) {
            int col = wn * 32 + j * 8 + (lid & 3) * 2;
            *(float2*)(stile + r0 * 128 + col)       = make_float2(acc[mt][j][0], acc[mt][j][1]);
            *(float2*)(stile + (r0 + 8) * 128 + col) = make_float2(acc[mt][j][2], acc[mt][j][3]);
        }
    }
    __syncthreads();

    const int pn = min(ecnt, ECAP);
    for (int e = wid; e < pn; e += 8) {
        int4 ed = sedge[e];
        float sc = __int_as_float(ed.z);
        const float4 v = *(const float4*)(stile + (ed.x - block_row) * 128 + lid * 4);
        float4* p = (float4*)(acc_out + (size_t)ed.y * HID) + lid;
        asm volatile("red.global.add.v4.f32 [%0], {%1, %2, %3, %4};"
                     :: "l"(p), "f"(v.x * sc), "f"(v.y * sc), "f"(v.z * sc), "f"(v.w * sc)
                     : "memory");
    }
    for (int e = ECAP + wid; e < ecnt; e += 8) {
        int4 ed = edge[e0 + e];
        float sc = __int_as_float(ed.z);
        const float4 v = *(const float4*)(stile + (ed.x - block_row) * 128 + lid * 4);
        float4* p = (float4*)(acc_out + (size_t)ed.y * HID) + lid;
        asm volatile("red.global.add.v4.f32 [%0], {%1, %2, %3, %4};"
                     :: "l"(p), "f"(v.x * sc), "f"(v.y * sc), "f"(v.z * sc), "f"(v.w * sc)
                     : "memory");
    }
}

// ---------------- launch ----------------
extern "C" void kernel_launch(void* const* d_in, const int* in_sizes, int n_in,
                              void* d_out, int out_size) {
    const int* edge_index = (const int*)d_in[0];
    const int* edge_type  = (const int*)d_in[1];
    const float* node_emb = (const float*)d_in[2];
    const float* W1    = (const float*)d_in[3];
    const float* root1 = (const float*)d_in[4];
    const float* b1    = (const float*)d_in[5];
    const float* W2    = (const float*)d_in[6];
    const float* root2 = (const float*)d_in[7];
    const float* b2    = (const float*)d_in[8];
    float* out = (float*)d_out;

    const int E = in_sizes[0] / 2;
    const int* src = edge_index;
    const int* dst = edge_index + E;

    float *t, *cnt;
    __nv_bfloat16 *xhi, *xlo, *bhi1, *blo1, *bhi2, *blo2;
    int *hist, *cur, *boff;
    int4* edge;
    cudaGetSymbolAddress((void**)&t,    g_t);
    cudaGetSymbolAddress((void**)&cnt,  g_cnt);
    cudaGetSymbolAddress((void**)&xhi,  g_xhi);
    cudaGetSymbolAddress((void**)&xlo,  g_xlo);
    cudaGetSymbolAddress((void**)&bhi1, g_bhi1);
    cudaGetSymbolAddress((void**)&blo1, g_blo1);
    cudaGetSymbolAddress((void**)&bhi2, g_bhi2);
    cudaGetSymbolAddress((void**)&blo2, g_blo2);
    cudaGetSymbolAddress((void**)&hist, g_hist);
    cudaGetSymbolAddress((void**)&cur,  g_cur);
    cudaGetSymbolAddress((void**)&boff, g_boff);
    cudaGetSymbolAddress((void**)&edge, g_edge);

    const int T = 256;
    const dim3 gemm_grid(9, NMB);
    const int SMEM_BYTES = 3 * STG + ECAP * 16;   // 106496
    cudaFuncSetAttribute(gemm_fused, cudaFuncAttributeMaxDynamicSharedMemorySize, SMEM_BYTES);

    // ---- prep ----
    cudaMemsetAsync(cnt, 0, sizeof(float) * (size_t)NN * NREL, 0);
    cudaMemsetAsync(hist, 0, sizeof(int) * NB2, 0);
    cudaMemsetAsync(cur, 0, sizeof(int) * NB2, 0);
    counthist_kernel<<<(E + T * 4 - 1) / (T * 4), T>>>(src, dst, edge_type, E, cnt, hist);
    scan_kernel<<<1, 1024>>>(hist, boff);
    prep_kernel<<<RBLK + 2 * BCONV_BLKS + BINIT_T_BLKS + BINIT_O_BLKS + XS_BLKS, T>>>(
        src, dst, edge_type, E, boff, cur, cnt, edge,
        W1, root1, W2, root2, b1, b2, bhi1, blo1, bhi2, blo2, t, out,
        node_emb, xhi, xlo);

    // ---- layer 1 ----
    gemm_fused<<<gemm_grid, T, SMEM_BYTES>>>(xhi, xlo, bhi1, blo1, t, NPAD, edge, boff);
    // ---- layer 2 ----
    xsplit2_kernel<<<XS_BLKS, T>>>(t, xhi, xlo);
    gemm_fused<<<gemm_grid, T, SMEM_BYTES>>>(xhi, xlo, bhi2, blo2, out, NN, edge, boff);
}